// round 5
// baseline (speedup 1.0000x reference)
#include <cuda_runtime.h>
#include <math.h>
#include <stdint.h>

#define FDIM 128
#define SSCALE 1.6666666666666667f   // 1/0.6
#define INV3 0.5773502691896258f     // 1/sqrt(3)
#define INVH 0.08838834764831845f    // 1/sqrt(128)

static __device__ float g_buf[127000000];

__device__ __forceinline__ float ssilu_f(float v) {
    return v * SSCALE / (1.0f + __expf(-v));
}

__device__ __forceinline__ float to_tf32_f(float x) {
    uint32_t r;
    asm("cvt.rna.tf32.f32 %0, %1;" : "=r"(r) : "f"(x));
    return __uint_as_float(r);
}

__device__ __forceinline__ float4 cvt4(float4 v) {
    return make_float4(to_tf32_f(v.x), to_tf32_f(v.y), to_tf32_f(v.z), to_tf32_f(v.w));
}

__device__ __forceinline__ uint32_t smem_to_u32(const void* smem_ptr) {
    uint32_t addr;
    asm("{ .reg .u64 tmp; cvta.to.shared.u64 tmp, %1; cvt.u32.u64 %0, tmp; }"
        : "=r"(addr) : "l"(smem_ptr));
    return addr;
}

__device__ __forceinline__ void ldsm_x4(uint32_t addr, uint32_t* r) {
    asm volatile("ldmatrix.sync.aligned.m8n8.x4.shared.b16 {%0,%1,%2,%3}, [%4];"
        : "=r"(r[0]), "=r"(r[1]), "=r"(r[2]), "=r"(r[3]) : "r"(addr));
}

__device__ __forceinline__ void mma_tf32(float* d, const uint32_t* a,
                                         const uint32_t* b, const float* c) {
    asm volatile(
        "mma.sync.aligned.m16n8k8.row.col.f32.tf32.tf32.f32 "
        "{%0,%1,%2,%3},{%4,%5,%6,%7},{%8,%9},{%10,%11,%12,%13};"
        : "=f"(d[0]), "=f"(d[1]), "=f"(d[2]), "=f"(d[3])
        : "r"(a[0]), "r"(a[1]), "r"(a[2]), "r"(a[3]),
          "r"(b[0]), "r"(b[1]),
          "f"(c[0]), "f"(c[1]), "f"(c[2]), "f"(c[3]));
}

// ---------------------------------------------------------------------------
// Weight transpose: WT[c*K + k] = W[k*Cc + c]  (coalesced writes)
// ---------------------------------------------------------------------------
__global__ void wtrans_k(const float* __restrict__ W, float* __restrict__ WT,
                         int K, int Cc)
{
    int id = blockIdx.x * 256 + threadIdx.x;
    if (id >= K * Cc) return;
    int k = id % K;
    int c = id / K;
    WT[id] = W[(size_t)k * Cc + c];
}

// ---------------------------------------------------------------------------
// ldmatrix-based tf32 GEMM: C[M,Cc] = A[M,K] @ W[K,Cc], W given TRANSPOSED
// (WT[Cc,K]). BM=128, BN=128, BK=16, 256 thr (8 warps 2Mx4N), warp 64x32.
// Smem: A[m][k], B[n][k], both in 16B-chunk XOR-swizzled row-major layout:
//   byte(row, chunk) = row*64 + ((chunk ^ ((row>>1)&3)) << 4)
// EPI: 0=plain 1=+bias 2=ssilu(+bias) 3=ssilu(+extra[bidx[r]*128+c])
//      4=ssilu(+bias)+extra[r*128+c] 6=(v+bias)*extra[r*Cc+c]*INV3
//      7=v+extra[r*128+c]+extra2[(bidx[r/3]*3+r%3)*128+c]
// ---------------------------------------------------------------------------
template <int EPI>
__global__ void __launch_bounds__(256, 2) lgemm_k(
    const float* __restrict__ A, const float* __restrict__ WT,
    const float* __restrict__ bias, float* __restrict__ C,
    int M, int K, int Cc,
    const float* __restrict__ extra, const float* __restrict__ extra2,
    const int* __restrict__ bidx)
{
    __shared__ float As[128 * 16];
    __shared__ float Bs[128 * 16];

    const int tid = threadIdx.x;
    const int warp = tid >> 5;
    const int lane = tid & 31;
    const int wm = warp & 1;
    const int wn = warp >> 1;
    const int g = lane >> 2;
    const int tig = lane & 3;
    const int row0 = blockIdx.y * 128;
    const int col0 = blockIdx.x * 128;

    const uint32_t as_b = smem_to_u32(As);
    const uint32_t bs_b = smem_to_u32(Bs);

    // loader geometry: 2 float4 tasks each for A and B
    const int l_row = tid >> 2;     // 0..63 ; second task row +64
    const int l_c = tid & 3;        // 16B chunk 0..3

    // LDSM per-lane address components
    const uint32_t a_hi = lane >> 4;          // 0/1 -> chunk +0/+1
    const uint32_t b_hi = (lane >> 3) & 1;
    uint32_t a_row64[4], a_sw[4];
    #pragma unroll
    for (int mi = 0; mi < 4; mi++) {
        int row = wm * 64 + mi * 16 + (lane & 15);
        a_row64[mi] = as_b + row * 64;
        a_sw[mi] = (row >> 1) & 3;
    }
    uint32_t b_row64[2], b_sw[2];
    #pragma unroll
    for (int p = 0; p < 2; p++) {
        int row = wn * 32 + p * 16 + (lane & 7) + ((lane >> 4) ? 8 : 0);
        b_row64[p] = bs_b + row * 64;
        b_sw[p] = (row >> 1) & 3;
    }

    float acc[4][4][4];
    #pragma unroll
    for (int i = 0; i < 4; i++)
        #pragma unroll
        for (int j = 0; j < 4; j++)
            #pragma unroll
            for (int q = 0; q < 4; q++) acc[i][j][q] = 0.0f;

    for (int k0 = 0; k0 < K; k0 += 16) {
        float4 av[2], wv[2];
        #pragma unroll
        for (int t = 0; t < 2; t++) {
            int row = l_row + t * 64;
            int ga = row0 + row;
            if (ga >= M) ga = M - 1;            // clamp; rows >= M never stored
            av[t] = *reinterpret_cast<const float4*>(A + (size_t)ga * K + k0 + l_c * 4);
            wv[t] = *reinterpret_cast<const float4*>(WT + (size_t)(col0 + row) * K + k0 + l_c * 4);
        }
        __syncthreads();   // previous iter's fragment reads complete
        #pragma unroll
        for (int t = 0; t < 2; t++) {
            int row = l_row + t * 64;
            uint32_t off = row * 64 + ((uint32_t)(l_c ^ ((row >> 1) & 3)) << 4);
            *reinterpret_cast<float4*>((char*)As + off) = cvt4(av[t]);
            *reinterpret_cast<float4*>((char*)Bs + off) = cvt4(wv[t]);
        }
        __syncthreads();

        #pragma unroll
        for (int s = 0; s < 2; s++) {
            uint32_t afr[4][4];
            #pragma unroll
            for (int mi = 0; mi < 4; mi++)
                ldsm_x4(a_row64[mi] + (((2 * s + a_hi) ^ a_sw[mi]) << 4), afr[mi]);
            uint32_t bfr[2][4];
            #pragma unroll
            for (int p = 0; p < 2; p++)
                ldsm_x4(b_row64[p] + (((2 * s + b_hi) ^ b_sw[p]) << 4), bfr[p]);
            #pragma unroll
            for (int mi = 0; mi < 4; mi++)
                #pragma unroll
                for (int nj = 0; nj < 4; nj++)
                    mma_tf32(acc[mi][nj], afr[mi],
                             &bfr[nj >> 1][(nj & 1) * 2], acc[mi][nj]);
        }
    }

    // Epilogue
    #pragma unroll
    for (int mi = 0; mi < 4; mi++) {
        int rbase = row0 + wm * 64 + mi * 16 + g;
        #pragma unroll
        for (int half = 0; half < 2; half++) {
            int r = rbase + half * 8;
            if (r >= M) continue;
            int rb = 0;
            if (EPI == 3) rb = bidx[r];
            size_t e2off = 0;
            if (EPI == 7) {
                int nnode = r / 3;
                e2off = ((size_t)bidx[nnode] * 3 + (r - nnode * 3)) * 128;
            }
            #pragma unroll
            for (int nj = 0; nj < 4; nj++) {
                int c = col0 + wn * 32 + nj * 8 + tig * 2;
                #pragma unroll
                for (int e = 0; e < 2; e++) {
                    float v = acc[mi][nj][half * 2 + e];
                    int cc = c + e;
                    if (EPI == 1) v += bias[cc];
                    else if (EPI == 2) v = ssilu_f(v + bias[cc]);
                    else if (EPI == 3) v = ssilu_f(v + extra[(size_t)rb * 128 + cc]);
                    else if (EPI == 4) v = ssilu_f(v + bias[cc]) + extra[(size_t)r * 128 + cc];
                    else if (EPI == 6) v = (v + bias[cc]) * extra[(size_t)r * Cc + cc] * INV3;
                    else if (EPI == 7) v = v + extra[(size_t)r * 128 + cc] + extra2[e2off + cc];
                    C[(size_t)r * Cc + cc] = v;
                }
            }
        }
    }
}

// ---------------------------------------------------------------------------
// mma.sync tf32 GEMM for small B-scale matrices (unchanged, known-good)
// ---------------------------------------------------------------------------
template <int EPI>
__global__ void __launch_bounds__(256) tgemm_k(
    const float* __restrict__ A, const float* __restrict__ W,
    const float* __restrict__ bias, float* __restrict__ C,
    int M, int K, int Cc,
    const float* __restrict__ extra, const int* __restrict__ bidx)
{
    __shared__ float As[16][136];
    __shared__ float Ws[16][136];

    const int tid = threadIdx.x;
    const int row0 = blockIdx.x * 128;
    const int col0 = blockIdx.y * 128;
    const int warp = tid >> 5;
    const int lane = tid & 31;
    const int wm = warp & 1;
    const int wn = warp >> 1;
    const int g = lane >> 2;
    const int tig = lane & 3;

    float acc[4][4][4];
    #pragma unroll
    for (int i = 0; i < 4; i++)
        #pragma unroll
        for (int j = 0; j < 4; j++)
            #pragma unroll
            for (int q = 0; q < 4; q++) acc[i][j][q] = 0.0f;

    for (int k0 = 0; k0 < K; k0 += 16) {
        #pragma unroll
        for (int t = 0; t < 2; t++) {
            int id = tid + t * 256;
            int row = id >> 2;
            int kc = (id & 3) * 4;
            float4 av;
            int grow = row0 + row;
            if (grow < M)
                av = *reinterpret_cast<const float4*>(A + (size_t)grow * K + k0 + kc);
            else
                av = make_float4(0.f, 0.f, 0.f, 0.f);
            As[kc + 0][row] = to_tf32_f(av.x);
            As[kc + 1][row] = to_tf32_f(av.y);
            As[kc + 2][row] = to_tf32_f(av.z);
            As[kc + 3][row] = to_tf32_f(av.w);
        }
        #pragma unroll
        for (int t = 0; t < 2; t++) {
            int id = tid + t * 256;
            int kr = id >> 5;
            int c4 = (id & 31) * 4;
            float4 wv = *reinterpret_cast<const float4*>(
                W + (size_t)(k0 + kr) * Cc + col0 + c4);
            Ws[kr][c4 + 0] = to_tf32_f(wv.x);
            Ws[kr][c4 + 1] = to_tf32_f(wv.y);
            Ws[kr][c4 + 2] = to_tf32_f(wv.z);
            Ws[kr][c4 + 3] = to_tf32_f(wv.w);
        }
        __syncthreads();

        #pragma unroll
        for (int s = 0; s < 2; s++) {
            const int kb = s * 8;
            uint32_t afr[4][4];
            uint32_t bfr[4][2];
            #pragma unroll
            for (int mi = 0; mi < 4; mi++) {
                int mr = wm * 64 + mi * 16 + g;
                afr[mi][0] = __float_as_uint(As[kb + tig][mr]);
                afr[mi][1] = __float_as_uint(As[kb + tig][mr + 8]);
                afr[mi][2] = __float_as_uint(As[kb + tig + 4][mr]);
                afr[mi][3] = __float_as_uint(As[kb + tig + 4][mr + 8]);
            }
            #pragma unroll
            for (int nj = 0; nj < 4; nj++) {
                int nc = wn * 32 + nj * 8 + g;
                bfr[nj][0] = __float_as_uint(Ws[kb + tig][nc]);
                bfr[nj][1] = __float_as_uint(Ws[kb + tig + 4][nc]);
            }
            #pragma unroll
            for (int mi = 0; mi < 4; mi++)
                #pragma unroll
                for (int nj = 0; nj < 4; nj++)
                    mma_tf32(acc[mi][nj], afr[mi], bfr[nj], acc[mi][nj]);
        }
        __syncthreads();
    }

    #pragma unroll
    for (int mi = 0; mi < 4; mi++) {
        int rbase = row0 + wm * 64 + mi * 16 + g;
        #pragma unroll
        for (int half = 0; half < 2; half++) {
            int r = rbase + half * 8;
            if (r >= M) continue;
            int rb = 0;
            if (EPI == 3) rb = bidx[r];
            #pragma unroll
            for (int nj = 0; nj < 4; nj++) {
                int c = col0 + wn * 32 + nj * 8 + tig * 2;
                #pragma unroll
                for (int e = 0; e < 2; e++) {
                    float v = acc[mi][nj][half * 2 + e];
                    int cc = c + e;
                    if (EPI == 1) v += bias[cc];
                    else if (EPI == 2) v = ssilu_f(v + bias[cc]);
                    else if (EPI == 3) v = ssilu_f(v + extra[(size_t)rb * 128 + cc]);
                    else if (EPI == 4) v = ssilu_f(v + bias[cc]) + extra[(size_t)r * 128 + cc];
                    else if (EPI == 5) v = v + extra[(size_t)r * 128 + cc];
                    C[(size_t)r * Cc + cc] = v;
                }
            }
        }
    }
}

// ---------------------------------------------------------------------------
// Node elementwise: p already = xp*ep*INV3. Writes xn and vecn only.
// ---------------------------------------------------------------------------
__global__ void node_elem_k(
    const float* p, const float* x,
    const float* vec, const float* ud,
    float* xn, float* vecn, int N)
{
    int idx = blockIdx.x * blockDim.x + threadIdx.x;
    if (idx >= N * FDIM) return;
    int n = idx >> 7;
    int f = idx & 127;
    size_t b3 = (size_t)n * 384;

    float p1 = p[b3 + f], p2 = p[b3 + 128 + f], p3 = p[b3 + 256 + f];

    xn[(size_t)n * 128 + f] = p3 + x[(size_t)n * 128 + f];

    float u0 = ud[n * 3 + 0], u1 = ud[n * 3 + 1], u2 = ud[n * 3 + 2];
    float v0 = vec[b3 + 0 * 128 + f];
    float v1 = vec[b3 + 1 * 128 + f];
    float v2 = vec[b3 + 2 * 128 + f];

    vecn[b3 + 0 * 128 + f] = (p1 * v0 + p2 * u0) * INVH;
    vecn[b3 + 1 * 128 + f] = (p1 * v1 + p2 * u1) * INVH;
    vecn[b3 + 2 * 128 + f] = (p1 * v2 + p2 * u2) * INVH;
}

__global__ void zero_k(float* p, int n) {
    int i = blockIdx.x * blockDim.x + threadIdx.x;
    if (i < n) p[i] = 0.0f;
}

__global__ void counts_k(const int* batch, float* cnt, int N) {
    int i = blockIdx.x * blockDim.x + threadIdx.x;
    if (i < N) atomicAdd(&cnt[batch[i]], 1.0f);
}

__global__ void seg_reduce_k(const float* src, const int* batch, float* dst,
                             int N, int Cc, int rows_per_blk)
{
    int c = threadIdx.x;
    int r0 = blockIdx.x * rows_per_blk;
    if (r0 >= N) return;
    int r1 = min(r0 + rows_per_blk, N);
    int cur = batch[r0];
    float s = 0.0f;
    for (int r = r0; r < r1; r++) {
        int b = batch[r];
        if (b != cur) {
            atomicAdd(&dst[(size_t)cur * Cc + c], s);
            s = 0.0f;
            cur = b;
        }
        s += src[(size_t)r * Cc + c];
    }
    atomicAdd(&dst[(size_t)cur * Cc + c], s);
}

__global__ void g1_k(const float* sum_x, const float* sum_vec, const float* cnt,
                     const float* scalar_l, const float* vector_l,
                     float* gcat, float* Av, int B)
{
    int idx = blockIdx.x * blockDim.x + threadIdx.x;
    if (idx >= B * 128) return;
    int b = idx >> 7, f = idx & 127;
    float invc = 1.0f / fmaxf(cnt[b], 1.0f);
    gcat[(size_t)b * 256 + f] = sum_x[(size_t)b * 128 + f] * invc;
    gcat[(size_t)b * 256 + 128 + f] = scalar_l[(size_t)b * 128 + f];
    #pragma unroll
    for (int d = 0; d < 3; d++) {
        size_t o = (size_t)b * 384 + d * 128 + f;
        Av[o] = sum_vec[o] * invc + vector_l[o];
    }
}

__global__ void g2_k(const float* scalar_l, const float* stmp,
                     const float* vector_l, const float* vtmpB,
                     float* sl, float* vl, int B)
{
    int idx = blockIdx.x * blockDim.x + threadIdx.x;
    if (idx >= B * 128) return;
    int b = idx >> 7, f = idx & 127;
    sl[(size_t)b * 128 + f] = scalar_l[(size_t)b * 128 + f] + stmp[(size_t)b * 128 + f];
    #pragma unroll
    for (int d = 0; d < 3; d++) {
        size_t o = (size_t)b * 384 + d * 128 + f;
        vl[o] = vector_l[o] + vtmpB[o];
    }
}

__global__ void g3_k(const float* hh, const float* sl, float* cat2, int B)
{
    int idx = blockIdx.x * blockDim.x + threadIdx.x;
    if (idx >= B * 128) return;
    int b = idx >> 7, f = idx & 127;
    float s = 1e-8f;
    #pragma unroll
    for (int d = 0; d < 3; d++) {
        float h2 = hh[((size_t)b * 3 + d) * 256 + 128 + f];
        s += h2 * h2;
    }
    cat2[(size_t)b * 256 + f] = sl[(size_t)b * 128 + f];
    cat2[(size_t)b * 256 + 128 + f] = sqrtf(s);
}

__global__ void g4_k(const float* sh, const float* sl, const float* hh,
                     const float* vl, float* out_sl, float* out_vl, int B)
{
    int idx = blockIdx.x * blockDim.x + threadIdx.x;
    if (idx >= B * 128) return;
    int b = idx >> 7, f = idx & 127;
    float s1 = sh[(size_t)b * 384 + f];
    float s2 = sh[(size_t)b * 384 + 128 + f];
    float s3 = sh[(size_t)b * 384 + 256 + f];
    out_sl[(size_t)b * 128 + f] = s2 + sl[(size_t)b * 128 + f] * tanhf(s3);
    #pragma unroll
    for (int d = 0; d < 3; d++) {
        float h1 = hh[((size_t)b * 3 + d) * 256 + f];
        size_t o = (size_t)b * 384 + d * 128 + f;
        out_vl[o] = s1 * h1 + vl[o];
    }
}

__global__ void ldelta_k(const float* vl_out, const float* W_ml, float* out, int rows)
{
    int warp = (blockIdx.x * blockDim.x + threadIdx.x) >> 5;
    int lane = threadIdx.x & 31;
    if (warp >= rows) return;
    const float* r = vl_out + (size_t)warp * 128;
    float s = 0.0f;
    #pragma unroll
    for (int i = 0; i < 4; i++) s += r[lane + i * 32] * W_ml[lane + i * 32];
    #pragma unroll
    for (int o = 16; o; o >>= 1) s += __shfl_down_sync(0xffffffff, s, o);
    if (lane == 0) out[warp] = s;
}

// ---------------------------------------------------------------------------
extern "C" void kernel_launch(void* const* d_in, const int* in_sizes, int n_in,
                              void* d_out, int out_size)
{
    const float* x        = (const float*)d_in[0];
    const float* scalar_l = (const float*)d_in[1];
    const float* vec      = (const float*)d_in[2];
    const float* vector_l = (const float*)d_in[3];
    const float* edge_f   = (const float*)d_in[4];
    const float* edge_ud  = (const float*)d_in[5];
    const int*   batch    = (const int*)d_in[6];
    const float* W_sg1 = (const float*)d_in[7];  const float* b_sg1 = (const float*)d_in[8];
    const float* W_sg2 = (const float*)d_in[9];  const float* b_sg2 = (const float*)d_in[10];
    const float* W_sl1 = (const float*)d_in[11]; const float* b_sl1 = (const float*)d_in[12];
    const float* W_sl2 = (const float*)d_in[13]; const float* b_sl2 = (const float*)d_in[14];
    const float* W_vg  = (const float*)d_in[15];
    const float* W_vl  = (const float*)d_in[16];
    const float* W_xp1 = (const float*)d_in[17]; const float* b_xp1 = (const float*)d_in[18];
    const float* W_xp2 = (const float*)d_in[19]; const float* b_xp2 = (const float*)d_in[20];
    const float* W_ep  = (const float*)d_in[21]; const float* b_ep  = (const float*)d_in[22];
    const float* W_vp  = (const float*)d_in[23];
    const float* W_lp1 = (const float*)d_in[24]; const float* b_lp1 = (const float*)d_in[25];
    const float* W_lp2 = (const float*)d_in[26]; const float* b_lp2 = (const float*)d_in[27];
    const float* W_ml  = (const float*)d_in[28];

    const int N = in_sizes[0] / FDIM;
    const int B = in_sizes[1] / FDIM;
    const int K_edge = in_sizes[4] / N;   // 64

    float* base = nullptr;
    cudaGetSymbolAddress((void**)&base, g_buf);

    const size_t NF = (size_t)N * FDIM;
    float* t_buf  = base;                 // [N,F]   t, later u
    float* xp_buf = base + NF;            // [N,3F]  xp -> p
    float* ep_buf = base + 4 * NF;        // [N,3F]  vecn
    float* xn_buf = base + 7 * NF;        // [N,F]
    float* sm     = base + 8 * NF;
    float* sB      = sm;
    float* sum_x   = sm + 65536;
    float* sum_vec = sm + 131072;
    float* cnt     = sm + 327680;
    float* gcat    = sm + 328192;
    float* Av      = sm + 459264;
    float* tmp1    = sm + 655872;
    float* stmp    = sm + 721408;
    float* vtmpB   = sm + 786944;
    float* sl      = sm + 983552;
    float* vl      = sm + 1049088;
    float* hh      = sm + 1245696;
    float* cat2    = sm + 1638912;
    float* t2      = sm + 1769984;
    float* sh      = sm + 1835520;
    float* VB      = sm + 2032128;          // [3B,128]
    float* wt_xp1  = sm + 2228736;          // 128*128
    float* wt_xp2  = sm + 2245120;          // 384*128
    float* wt_ep   = sm + 2294272;          // 384*64
    float* wt_sl1  = sm + 2318848;          // 128*128 (first half of W_sl1)
    float* wt_sl2  = sm + 2335232;          // 128*128
    float* wt_vl   = sm + 2351616;          // 128*128

    float* out = (float*)d_out;
    const size_t o0 = 0;
    const size_t o1 = NF;
    const size_t o2 = o1 + 3 * NF;
    const size_t o3 = o2 + (size_t)B * 128;
    const size_t o4 = o3 + (size_t)B * 384;

    const int rT_N  = (N + 127) / 128;
    const int rT_3N = (3 * N + 127) / 128;
    const int gM_B  = (B + 127) / 128;
    const int gM_3B = (3 * B + 127) / 128;

    // ---- transpose weights for lgemm ----
    wtrans_k<<<(128 * 128 + 255) / 256, 256>>>(W_xp1, wt_xp1, 128, 128);
    wtrans_k<<<(128 * 384 + 255) / 256, 256>>>(W_xp2, wt_xp2, 128, 384);
    wtrans_k<<<(K_edge * 384 + 255) / 256, 256>>>(W_ep, wt_ep, K_edge, 384);
    wtrans_k<<<(128 * 128 + 255) / 256, 256>>>(W_sl1, wt_sl1, 128, 128);
    wtrans_k<<<(128 * 128 + 255) / 256, 256>>>(W_sl2, wt_sl2, 128, 128);
    wtrans_k<<<(128 * 128 + 255) / 256, 256>>>(W_vl, wt_vl, 128, 128);

    // VB = vector_l @ W_vl  (small)
    tgemm_k<0><<<dim3(gM_3B, 1), 256>>>(vector_l, W_vl, nullptr, VB, 3 * B, 128, 128, nullptr, nullptr);
    // sB = scalar_l @ W_sl1[F:] + b_sl1  (small)
    tgemm_k<1><<<dim3(gM_B, 1), 256>>>(scalar_l, W_sl1 + 128 * 128, b_sl1, sB, B, 128, 128, nullptr, nullptr);

    // ---- node phase ----
    // t = ssilu(x @ W_xp1 + b_xp1)
    lgemm_k<2><<<dim3(1, rT_N), 256>>>(x, wt_xp1, b_xp1, t_buf, N, 128, 128, nullptr, nullptr, nullptr);
    // xp = t @ W_xp2 + b_xp2
    lgemm_k<1><<<dim3(3, rT_N), 256>>>(t_buf, wt_xp2, b_xp2, xp_buf, N, 128, 384, nullptr, nullptr, nullptr);
    // p = (edge_feat @ W_ep + b_ep) * xp * INV3  (in place over xp_buf)
    lgemm_k<6><<<dim3(3, rT_N), 256>>>(edge_f, wt_ep, b_ep, xp_buf, N, K_edge, 384, xp_buf, nullptr, nullptr);
    // xn, vecn
    {
        int tot = N * FDIM;
        node_elem_k<<<(tot + 255) / 256, 256>>>(xp_buf, x, vec, edge_ud, xn_buf, ep_buf, N);
    }
    // u = ssilu(xn @ W_sl1[:F] + sB[batch])
    lgemm_k<3><<<dim3(1, rT_N), 256>>>(xn_buf, wt_sl1, nullptr, t_buf, N, 128, 128, sB, nullptr, batch);
    // hx = ssilu(u @ W_sl2 + b_sl2) + xn
    lgemm_k<4><<<dim3(1, rT_N), 256>>>(t_buf, wt_sl2, b_sl2, out + o0, N, 128, 128, xn_buf, nullptr, nullptr);
    // hvec = vecn @ W_vl + vecn + VB[batch]
    lgemm_k<7><<<dim3(1, rT_3N), 256>>>(ep_buf, wt_vl, nullptr, out + o1, 3 * N, 128, 128, ep_buf, VB, batch);

    // ---- segment reduction ----
    {
        int nz = B * 128 + B * 384 + B;
        zero_k<<<(nz + 255) / 256, 256>>>(sum_x, nz);
        counts_k<<<(N + 255) / 256, 256>>>(batch, cnt, N);
        int rpb1 = 256;
        seg_reduce_k<<<(N + rpb1 - 1) / rpb1, 128>>>(out + o0, batch, sum_x, N, 128, rpb1);
        int rpb2 = 128;
        seg_reduce_k<<<(N + rpb2 - 1) / rpb2, 384>>>(out + o1, batch, sum_vec, N, 384, rpb2);
    }

    // ---- global phase (small) ----
    int tB = B * 128;
    g1_k<<<(tB + 255) / 256, 256>>>(sum_x, sum_vec, cnt, scalar_l, vector_l, gcat, Av, B);
    tgemm_k<2><<<dim3(gM_B, 1), 256>>>(gcat, W_sg1, b_sg1, tmp1, B, 256, 128, nullptr, nullptr);
    tgemm_k<2><<<dim3(gM_B, 1), 256>>>(tmp1, W_sg2, b_sg2, stmp, B, 128, 128, nullptr, nullptr);
    tgemm_k<0><<<dim3(gM_3B, 1), 256>>>(Av, W_vg, nullptr, vtmpB, 3 * B, 128, 128, nullptr, nullptr);
    g2_k<<<(tB + 255) / 256, 256>>>(scalar_l, stmp, vector_l, vtmpB, sl, vl, B);
    tgemm_k<0><<<dim3(gM_3B, 2), 256>>>(vl, W_vp, nullptr, hh, 3 * B, 128, 256, nullptr, nullptr);
    g3_k<<<(tB + 255) / 256, 256>>>(hh, sl, cat2, B);
    tgemm_k<2><<<dim3(gM_B, 1), 256>>>(cat2, W_lp1, b_lp1, t2, B, 256, 128, nullptr, nullptr);
    tgemm_k<1><<<dim3(gM_B, 3), 256>>>(t2, W_lp2, b_lp2, sh, B, 128, 384, nullptr, nullptr);
    g4_k<<<(tB + 255) / 256, 256>>>(sh, sl, hh, vl, out + o2, out + o3, B);
    {
        int rows = 3 * B;
        int thr = 256;
        int blks = (rows * 32 + thr - 1) / thr;
        ldelta_k<<<blks, thr>>>(out + o3, W_ml, out + o4, rows);
    }
}

// round 7
// speedup vs baseline: 1.0881x; 1.0881x over previous
#include <cuda_runtime.h>
#include <cuda_fp16.h>
#include <math.h>
#include <stdint.h>

#define FDIM 128
#define SSCALE 1.6666666666666667f   // 1/0.6
#define INV3 0.5773502691896258f     // 1/sqrt(3)
#define INVH 0.08838834764831845f    // 1/sqrt(128)

static __device__ float g_buf[127000000];

__device__ __forceinline__ float ssilu_f(float v) {
    return v * SSCALE / (1.0f + __expf(-v));
}

__device__ __forceinline__ float to_tf32_f(float x) {
    uint32_t r;
    asm("cvt.rna.tf32.f32 %0, %1;" : "=r"(r) : "f"(x));
    return __uint_as_float(r);
}

__device__ __forceinline__ uint32_t pack_h2(float a, float b) {
    __half2 h = __floats2half2_rn(a, b);
    return *reinterpret_cast<uint32_t*>(&h);
}

__device__ __forceinline__ uint32_t smem_to_u32(const void* smem_ptr) {
    uint32_t addr;
    asm("{ .reg .u64 tmp; cvta.to.shared.u64 tmp, %1; cvt.u32.u64 %0, tmp; }"
        : "=r"(addr) : "l"(smem_ptr));
    return addr;
}

__device__ __forceinline__ void ldsm_x4(uint32_t addr, uint32_t* r) {
    asm volatile("ldmatrix.sync.aligned.m8n8.x4.shared.b16 {%0,%1,%2,%3}, [%4];"
        : "=r"(r[0]), "=r"(r[1]), "=r"(r[2]), "=r"(r[3]) : "r"(addr));
}

__device__ __forceinline__ void mma_f16(float* d, const uint32_t* a,
                                        const uint32_t* b, const float* c) {
    asm volatile(
        "mma.sync.aligned.m16n8k16.row.col.f32.f16.f16.f32 "
        "{%0,%1,%2,%3},{%4,%5,%6,%7},{%8,%9},{%10,%11,%12,%13};"
        : "=f"(d[0]), "=f"(d[1]), "=f"(d[2]), "=f"(d[3])
        : "r"(a[0]), "r"(a[1]), "r"(a[2]), "r"(a[3]),
          "r"(b[0]), "r"(b[1]),
          "f"(c[0]), "f"(c[1]), "f"(c[2]), "f"(c[3]));
}

__device__ __forceinline__ void mma_tf32(float* d, const uint32_t* a,
                                         const uint32_t* b, const float* c) {
    asm volatile(
        "mma.sync.aligned.m16n8k8.row.col.f32.tf32.tf32.f32 "
        "{%0,%1,%2,%3},{%4,%5,%6,%7},{%8,%9},{%10,%11,%12,%13};"
        : "=f"(d[0]), "=f"(d[1]), "=f"(d[2]), "=f"(d[3])
        : "r"(a[0]), "r"(a[1]), "r"(a[2]), "r"(a[3]),
          "r"(b[0]), "r"(b[1]),
          "f"(c[0]), "f"(c[1]), "f"(c[2]), "f"(c[3]));
}

// ---------------------------------------------------------------------------
// Weight transpose: WT[c*K + k] = W[k*Cc + c]
// ---------------------------------------------------------------------------
__global__ void wtrans_k(const float* __restrict__ W, float* __restrict__ WT,
                         int K, int Cc)
{
    int id = blockIdx.x * 256 + threadIdx.x;
    if (id >= K * Cc) return;
    int k = id % K;
    int c = id / K;
    WT[id] = W[(size_t)k * Cc + c];
}

// ---------------------------------------------------------------------------
// fp16 ldmatrix GEMM: C[M,Cc] = A[M,K] @ W[K,Cc], W given TRANSPOSED (WT[Cc,K])
// BM=128, BN=128, BK=32, 256 thr (8 warps 2Mx4N), warp tile 64x32.
// fp32 accumulate. Smem rows = 64B = 32 fp16, 16B-chunk XOR swizzle:
//   byte(row, chunk) = row*64 + ((chunk ^ ((row>>1)&3)) << 4)
// EPI: 0=plain 1=+bias 2=ssilu(+bias) 3=ssilu(+extra[bidx[r]*128+c])
//      4=ssilu(+bias)+extra[r*128+c] 6=(v+bias)*extra[r*Cc+c]*INV3
//      7=v+extra[r*128+c]+extra2[(bidx[r/3]*3+r%3)*128+c]
// Requires K % 32 == 0.
// ---------------------------------------------------------------------------
template <int EPI>
__global__ void __launch_bounds__(256, 2) hgemm_k(
    const float* __restrict__ A, const float* __restrict__ WT,
    const float* __restrict__ bias, float* __restrict__ C,
    int M, int K, int Cc,
    const float* __restrict__ extra, const float* __restrict__ extra2,
    const int* __restrict__ bidx)
{
    __shared__ uint32_t As[128 * 16];   // 128 rows x 64B
    __shared__ uint32_t Bs[128 * 16];

    const int tid = threadIdx.x;
    const int warp = tid >> 5;
    const int lane = tid & 31;
    const int wm = warp & 1;
    const int wn = warp >> 1;
    const int g = lane >> 2;
    const int tig = lane & 3;
    const int row0 = blockIdx.y * 128;
    const int col0 = blockIdx.x * 128;

    const uint32_t as_b = smem_to_u32(As);
    const uint32_t bs_b = smem_to_u32(Bs);

    // loader geometry: task id -> (row, 16B chunk); 2 tasks each for A and B
    const int l_row = tid >> 2;     // second task: +64
    const int l_c = tid & 3;

    // LDSM per-lane address components
    const uint32_t a_hi = lane >> 4;
    const uint32_t b_hi = (lane >> 3) & 1;
    uint32_t a_row64[4], a_sw[4];
    #pragma unroll
    for (int mi = 0; mi < 4; mi++) {
        int row = wm * 64 + mi * 16 + (lane & 15);
        a_row64[mi] = as_b + row * 64;
        a_sw[mi] = (row >> 1) & 3;
    }
    uint32_t b_row64[2], b_sw[2];
    #pragma unroll
    for (int p = 0; p < 2; p++) {
        int row = wn * 32 + p * 16 + (lane & 7) + ((lane >> 4) ? 8 : 0);
        b_row64[p] = bs_b + row * 64;
        b_sw[p] = (row >> 1) & 3;
    }

    float acc[4][4][4];
    #pragma unroll
    for (int i = 0; i < 4; i++)
        #pragma unroll
        for (int j = 0; j < 4; j++)
            #pragma unroll
            for (int q = 0; q < 4; q++) acc[i][j][q] = 0.0f;

    for (int k0 = 0; k0 < K; k0 += 32) {
        uint4 av[2], bv[2];
        #pragma unroll
        for (int t = 0; t < 2; t++) {
            int row = l_row + t * 64;
            int ga = row0 + row;
            if (ga >= M) ga = M - 1;            // clamp; rows >= M never stored
            const float* ap = A + (size_t)ga * K + k0 + l_c * 8;
            float4 a1 = *reinterpret_cast<const float4*>(ap);
            float4 a2 = *reinterpret_cast<const float4*>(ap + 4);
            av[t] = make_uint4(pack_h2(a1.x, a1.y), pack_h2(a1.z, a1.w),
                               pack_h2(a2.x, a2.y), pack_h2(a2.z, a2.w));
            const float* bp = WT + (size_t)(col0 + row) * K + k0 + l_c * 8;
            float4 b1 = *reinterpret_cast<const float4*>(bp);
            float4 b2 = *reinterpret_cast<const float4*>(bp + 4);
            bv[t] = make_uint4(pack_h2(b1.x, b1.y), pack_h2(b1.z, b1.w),
                               pack_h2(b2.x, b2.y), pack_h2(b2.z, b2.w));
        }
        __syncthreads();   // previous iter's fragment reads complete
        #pragma unroll
        for (int t = 0; t < 2; t++) {
            int row = l_row + t * 64;
            uint32_t off = row * 64 + ((uint32_t)(l_c ^ ((row >> 1) & 3)) << 4);
            *reinterpret_cast<uint4*>((char*)As + off) = av[t];
            *reinterpret_cast<uint4*>((char*)Bs + off) = bv[t];
        }
        __syncthreads();

        #pragma unroll
        for (int s = 0; s < 2; s++) {   // k-step of 16 (chunks 2s, 2s+1)
            uint32_t afr[4][4];
            #pragma unroll
            for (int mi = 0; mi < 4; mi++)
                ldsm_x4(a_row64[mi] + (((2 * s + a_hi) ^ a_sw[mi]) << 4), afr[mi]);
            uint32_t bfr[2][4];
            #pragma unroll
            for (int p = 0; p < 2; p++)
                ldsm_x4(b_row64[p] + (((2 * s + b_hi) ^ b_sw[p]) << 4), bfr[p]);
            #pragma unroll
            for (int mi = 0; mi < 4; mi++)
                #pragma unroll
                for (int nj = 0; nj < 4; nj++)
                    mma_f16(acc[mi][nj], afr[mi],
                            &bfr[nj >> 1][(nj & 1) * 2], acc[mi][nj]);
        }
    }

    // Epilogue
    #pragma unroll
    for (int mi = 0; mi < 4; mi++) {
        int rbase = row0 + wm * 64 + mi * 16 + g;
        #pragma unroll
        for (int half = 0; half < 2; half++) {
            int r = rbase + half * 8;
            if (r >= M) continue;
            int rb = 0;
            if (EPI == 3) rb = bidx[r];
            size_t e2off = 0;
            if (EPI == 7) {
                int nnode = r / 3;
                e2off = ((size_t)bidx[nnode] * 3 + (r - nnode * 3)) * 128;
            }
            #pragma unroll
            for (int nj = 0; nj < 4; nj++) {
                int c = col0 + wn * 32 + nj * 8 + tig * 2;
                #pragma unroll
                for (int e = 0; e < 2; e++) {
                    float v = acc[mi][nj][half * 2 + e];
                    int cc = c + e;
                    if (EPI == 1) v += bias[cc];
                    else if (EPI == 2) v = ssilu_f(v + bias[cc]);
                    else if (EPI == 3) v = ssilu_f(v + extra[(size_t)rb * 128 + cc]);
                    else if (EPI == 4) v = ssilu_f(v + bias[cc]) + extra[(size_t)r * 128 + cc];
                    else if (EPI == 6) v = (v + bias[cc]) * extra[(size_t)r * Cc + cc] * INV3;
                    else if (EPI == 7) v = v + extra[(size_t)r * 128 + cc] + extra2[e2off + cc];
                    C[(size_t)r * Cc + cc] = v;
                }
            }
        }
    }
}

// ---------------------------------------------------------------------------
// mma.sync tf32 GEMM for small B-scale matrices (unchanged, known-good)
// ---------------------------------------------------------------------------
template <int EPI>
__global__ void __launch_bounds__(256) tgemm_k(
    const float* __restrict__ A, const float* __restrict__ W,
    const float* __restrict__ bias, float* __restrict__ C,
    int M, int K, int Cc,
    const float* __restrict__ extra, const int* __restrict__ bidx)
{
    __shared__ float As[16][136];
    __shared__ float Ws[16][136];

    const int tid = threadIdx.x;
    const int row0 = blockIdx.x * 128;
    const int col0 = blockIdx.y * 128;
    const int warp = tid >> 5;
    const int lane = tid & 31;
    const int wm = warp & 1;
    const int wn = warp >> 1;
    const int g = lane >> 2;
    const int tig = lane & 3;

    float acc[4][4][4];
    #pragma unroll
    for (int i = 0; i < 4; i++)
        #pragma unroll
        for (int j = 0; j < 4; j++)
            #pragma unroll
            for (int q = 0; q < 4; q++) acc[i][j][q] = 0.0f;

    for (int k0 = 0; k0 < K; k0 += 16) {
        #pragma unroll
        for (int t = 0; t < 2; t++) {
            int id = tid + t * 256;
            int row = id >> 2;
            int kc = (id & 3) * 4;
            float4 av;
            int grow = row0 + row;
            if (grow < M)
                av = *reinterpret_cast<const float4*>(A + (size_t)grow * K + k0 + kc);
            else
                av = make_float4(0.f, 0.f, 0.f, 0.f);
            As[kc + 0][row] = to_tf32_f(av.x);
            As[kc + 1][row] = to_tf32_f(av.y);
            As[kc + 2][row] = to_tf32_f(av.z);
            As[kc + 3][row] = to_tf32_f(av.w);
        }
        #pragma unroll
        for (int t = 0; t < 2; t++) {
            int id = tid + t * 256;
            int kr = id >> 5;
            int c4 = (id & 31) * 4;
            float4 wv = *reinterpret_cast<const float4*>(
                W + (size_t)(k0 + kr) * Cc + col0 + c4);
            Ws[kr][c4 + 0] = to_tf32_f(wv.x);
            Ws[kr][c4 + 1] = to_tf32_f(wv.y);
            Ws[kr][c4 + 2] = to_tf32_f(wv.z);
            Ws[kr][c4 + 3] = to_tf32_f(wv.w);
        }
        __syncthreads();

        #pragma unroll
        for (int s = 0; s < 2; s++) {
            const int kb = s * 8;
            uint32_t afr[4][4];
            uint32_t bfr[4][2];
            #pragma unroll
            for (int mi = 0; mi < 4; mi++) {
                int mr = wm * 64 + mi * 16 + g;
                afr[mi][0] = __float_as_uint(As[kb + tig][mr]);
                afr[mi][1] = __float_as_uint(As[kb + tig][mr + 8]);
                afr[mi][2] = __float_as_uint(As[kb + tig + 4][mr]);
                afr[mi][3] = __float_as_uint(As[kb + tig + 4][mr + 8]);
            }
            #pragma unroll
            for (int nj = 0; nj < 4; nj++) {
                int nc = wn * 32 + nj * 8 + g;
                bfr[nj][0] = __float_as_uint(Ws[kb + tig][nc]);
                bfr[nj][1] = __float_as_uint(Ws[kb + tig + 4][nc]);
            }
            #pragma unroll
            for (int mi = 0; mi < 4; mi++)
                #pragma unroll
                for (int nj = 0; nj < 4; nj++)
                    mma_tf32(acc[mi][nj], afr[mi], bfr[nj], acc[mi][nj]);
        }
        __syncthreads();
    }

    #pragma unroll
    for (int mi = 0; mi < 4; mi++) {
        int rbase = row0 + wm * 64 + mi * 16 + g;
        #pragma unroll
        for (int half = 0; half < 2; half++) {
            int r = rbase + half * 8;
            if (r >= M) continue;
            int rb = 0;
            if (EPI == 3) rb = bidx[r];
            #pragma unroll
            for (int nj = 0; nj < 4; nj++) {
                int c = col0 + wn * 32 + nj * 8 + tig * 2;
                #pragma unroll
                for (int e = 0; e < 2; e++) {
                    float v = acc[mi][nj][half * 2 + e];
                    int cc = c + e;
                    if (EPI == 1) v += bias[cc];
                    else if (EPI == 2) v = ssilu_f(v + bias[cc]);
                    else if (EPI == 3) v = ssilu_f(v + extra[(size_t)rb * 128 + cc]);
                    else if (EPI == 4) v = ssilu_f(v + bias[cc]) + extra[(size_t)r * 128 + cc];
                    else if (EPI == 5) v = v + extra[(size_t)r * 128 + cc];
                    C[(size_t)r * Cc + cc] = v;
                }
            }
        }
    }
}

// ---------------------------------------------------------------------------
__global__ void node_elem_k(
    const float* p, const float* x,
    const float* vec, const float* ud,
    float* xn, float* vecn, int N)
{
    int idx = blockIdx.x * blockDim.x + threadIdx.x;
    if (idx >= N * FDIM) return;
    int n = idx >> 7;
    int f = idx & 127;
    size_t b3 = (size_t)n * 384;

    float p1 = p[b3 + f], p2 = p[b3 + 128 + f], p3 = p[b3 + 256 + f];

    xn[(size_t)n * 128 + f] = p3 + x[(size_t)n * 128 + f];

    float u0 = ud[n * 3 + 0], u1 = ud[n * 3 + 1], u2 = ud[n * 3 + 2];
    float v0 = vec[b3 + 0 * 128 + f];
    float v1 = vec[b3 + 1 * 128 + f];
    float v2 = vec[b3 + 2 * 128 + f];

    vecn[b3 + 0 * 128 + f] = (p1 * v0 + p2 * u0) * INVH;
    vecn[b3 + 1 * 128 + f] = (p1 * v1 + p2 * u1) * INVH;
    vecn[b3 + 2 * 128 + f] = (p1 * v2 + p2 * u2) * INVH;
}

__global__ void zero_k(float* p, int n) {
    int i = blockIdx.x * blockDim.x + threadIdx.x;
    if (i < n) p[i] = 0.0f;
}

__global__ void counts_k(const int* batch, float* cnt, int N) {
    int i = blockIdx.x * blockDim.x + threadIdx.x;
    if (i < N) atomicAdd(&cnt[batch[i]], 1.0f);
}

__global__ void seg_reduce_k(const float* src, const int* batch, float* dst,
                             int N, int Cc, int rows_per_blk)
{
    int c = threadIdx.x;
    int r0 = blockIdx.x * rows_per_blk;
    if (r0 >= N) return;
    int r1 = min(r0 + rows_per_blk, N);
    int cur = batch[r0];
    float s = 0.0f;
    for (int r = r0; r < r1; r++) {
        int b = batch[r];
        if (b != cur) {
            atomicAdd(&dst[(size_t)cur * Cc + c], s);
            s = 0.0f;
            cur = b;
        }
        s += src[(size_t)r * Cc + c];
    }
    atomicAdd(&dst[(size_t)cur * Cc + c], s);
}

__global__ void g1_k(const float* sum_x, const float* sum_vec, const float* cnt,
                     const float* scalar_l, const float* vector_l,
                     float* gcat, float* Av, int B)
{
    int idx = blockIdx.x * blockDim.x + threadIdx.x;
    if (idx >= B * 128) return;
    int b = idx >> 7, f = idx & 127;
    float invc = 1.0f / fmaxf(cnt[b], 1.0f);
    gcat[(size_t)b * 256 + f] = sum_x[(size_t)b * 128 + f] * invc;
    gcat[(size_t)b * 256 + 128 + f] = scalar_l[(size_t)b * 128 + f];
    #pragma unroll
    for (int d = 0; d < 3; d++) {
        size_t o = (size_t)b * 384 + d * 128 + f;
        Av[o] = sum_vec[o] * invc + vector_l[o];
    }
}

__global__ void g2_k(const float* scalar_l, const float* stmp,
                     const float* vector_l, const float* vtmpB,
                     float* sl, float* vl, int B)
{
    int idx = blockIdx.x * blockDim.x + threadIdx.x;
    if (idx >= B * 128) return;
    int b = idx >> 7, f = idx & 127;
    sl[(size_t)b * 128 + f] = scalar_l[(size_t)b * 128 + f] + stmp[(size_t)b * 128 + f];
    #pragma unroll
    for (int d = 0; d < 3; d++) {
        size_t o = (size_t)b * 384 + d * 128 + f;
        vl[o] = vector_l[o] + vtmpB[o];
    }
}

__global__ void g3_k(const float* hh, const float* sl, float* cat2, int B)
{
    int idx = blockIdx.x * blockDim.x + threadIdx.x;
    if (idx >= B * 128) return;
    int b = idx >> 7, f = idx & 127;
    float s = 1e-8f;
    #pragma unroll
    for (int d = 0; d < 3; d++) {
        float h2 = hh[((size_t)b * 3 + d) * 256 + 128 + f];
        s += h2 * h2;
    }
    cat2[(size_t)b * 256 + f] = sl[(size_t)b * 128 + f];
    cat2[(size_t)b * 256 + 128 + f] = sqrtf(s);
}

__global__ void g4_k(const float* sh, const float* sl, const float* hh,
                     const float* vl, float* out_sl, float* out_vl, int B)
{
    int idx = blockIdx.x * blockDim.x + threadIdx.x;
    if (idx >= B * 128) return;
    int b = idx >> 7, f = idx & 127;
    float s1 = sh[(size_t)b * 384 + f];
    float s2 = sh[(size_t)b * 384 + 128 + f];
    float s3 = sh[(size_t)b * 384 + 256 + f];
    out_sl[(size_t)b * 128 + f] = s2 + sl[(size_t)b * 128 + f] * tanhf(s3);
    #pragma unroll
    for (int d = 0; d < 3; d++) {
        float h1 = hh[((size_t)b * 3 + d) * 256 + f];
        size_t o = (size_t)b * 384 + d * 128 + f;
        out_vl[o] = s1 * h1 + vl[o];
    }
}

__global__ void ldelta_k(const float* vl_out, const float* W_ml, float* out, int rows)
{
    int warp = (blockIdx.x * blockDim.x + threadIdx.x) >> 5;
    int lane = threadIdx.x & 31;
    if (warp >= rows) return;
    const float* r = vl_out + (size_t)warp * 128;
    float s = 0.0f;
    #pragma unroll
    for (int i = 0; i < 4; i++) s += r[lane + i * 32] * W_ml[lane + i * 32];
    #pragma unroll
    for (int o = 16; o; o >>= 1) s += __shfl_down_sync(0xffffffff, s, o);
    if (lane == 0) out[warp] = s;
}

// ---------------------------------------------------------------------------
extern "C" void kernel_launch(void* const* d_in, const int* in_sizes, int n_in,
                              void* d_out, int out_size)
{
    const float* x        = (const float*)d_in[0];
    const float* scalar_l = (const float*)d_in[1];
    const float* vec      = (const float*)d_in[2];
    const float* vector_l = (const float*)d_in[3];
    const float* edge_f   = (const float*)d_in[4];
    const float* edge_ud  = (const float*)d_in[5];
    const int*   batch    = (const int*)d_in[6];
    const float* W_sg1 = (const float*)d_in[7];  const float* b_sg1 = (const float*)d_in[8];
    const float* W_sg2 = (const float*)d_in[9];  const float* b_sg2 = (const float*)d_in[10];
    const float* W_sl1 = (const float*)d_in[11]; const float* b_sl1 = (const float*)d_in[12];
    const float* W_sl2 = (const float*)d_in[13]; const float* b_sl2 = (const float*)d_in[14];
    const float* W_vg  = (const float*)d_in[15];
    const float* W_vl  = (const float*)d_in[16];
    const float* W_xp1 = (const float*)d_in[17]; const float* b_xp1 = (const float*)d_in[18];
    const float* W_xp2 = (const float*)d_in[19]; const float* b_xp2 = (const float*)d_in[20];
    const float* W_ep  = (const float*)d_in[21]; const float* b_ep  = (const float*)d_in[22];
    const float* W_vp  = (const float*)d_in[23];
    const float* W_lp1 = (const float*)d_in[24]; const float* b_lp1 = (const float*)d_in[25];
    const float* W_lp2 = (const float*)d_in[26]; const float* b_lp2 = (const float*)d_in[27];
    const float* W_ml  = (const float*)d_in[28];

    const int N = in_sizes[0] / FDIM;
    const int B = in_sizes[1] / FDIM;
    const int K_edge = in_sizes[4] / N;   // 64

    float* base = nullptr;
    cudaGetSymbolAddress((void**)&base, g_buf);

    const size_t NF = (size_t)N * FDIM;
    float* t_buf  = base;                 // [N,F]   t, later u
    float* xp_buf = base + NF;            // [N,3F]  xp -> p
    float* ep_buf = base + 4 * NF;        // [N,3F]  vecn
    float* xn_buf = base + 7 * NF;        // [N,F]
    float* sm     = base + 8 * NF;
    float* sB      = sm;
    float* sum_x   = sm + 65536;
    float* sum_vec = sm + 131072;
    float* cnt     = sm + 327680;
    float* gcat    = sm + 328192;
    float* Av      = sm + 459264;
    float* tmp1    = sm + 655872;
    float* stmp    = sm + 721408;
    float* vtmpB   = sm + 786944;
    float* sl      = sm + 983552;
    float* vl      = sm + 1049088;
    float* hh      = sm + 1245696;
    float* cat2    = sm + 1638912;
    float* t2      = sm + 1769984;
    float* sh      = sm + 1835520;
    float* VB      = sm + 2032128;          // [3B,128]
    float* wt_xp1  = sm + 2228736;          // 128*128
    float* wt_xp2  = sm + 2245120;          // 384*128
    float* wt_ep   = sm + 2294272;          // 384*64
    float* wt_sl1  = sm + 2318848;          // 128*128 (first half of W_sl1)
    float* wt_sl2  = sm + 2335232;          // 128*128
    float* wt_vl   = sm + 2351616;          // 128*128

    float* out = (float*)d_out;
    const size_t o0 = 0;
    const size_t o1 = NF;
    const size_t o2 = o1 + 3 * NF;
    const size_t o3 = o2 + (size_t)B * 128;
    const size_t o4 = o3 + (size_t)B * 384;

    const int rT_N  = (N + 127) / 128;
    const int rT_3N = (3 * N + 127) / 128;
    const int gM_B  = (B + 127) / 128;
    const int gM_3B = (3 * B + 127) / 128;

    // ---- transpose weights for hgemm ----
    wtrans_k<<<(128 * 128 + 255) / 256, 256>>>(W_xp1, wt_xp1, 128, 128);
    wtrans_k<<<(128 * 384 + 255) / 256, 256>>>(W_xp2, wt_xp2, 128, 384);
    wtrans_k<<<(K_edge * 384 + 255) / 256, 256>>>(W_ep, wt_ep, K_edge, 384);
    wtrans_k<<<(128 * 128 + 255) / 256, 256>>>(W_sl1, wt_sl1, 128, 128);
    wtrans_k<<<(128 * 128 + 255) / 256, 256>>>(W_sl2, wt_sl2, 128, 128);
    wtrans_k<<<(128 * 128 + 255) / 256, 256>>>(W_vl, wt_vl, 128, 128);

    // VB = vector_l @ W_vl  (small)
    tgemm_k<0><<<dim3(gM_3B, 1), 256>>>(vector_l, W_vl, nullptr, VB, 3 * B, 128, 128, nullptr, nullptr);
    // sB = scalar_l @ W_sl1[F:] + b_sl1  (small)
    tgemm_k<1><<<dim3(gM_B, 1), 256>>>(scalar_l, W_sl1 + 128 * 128, b_sl1, sB, B, 128, 128, nullptr, nullptr);

    // ---- node phase (fp16 tensor cores) ----
    // t = ssilu(x @ W_xp1 + b_xp1)
    hgemm_k<2><<<dim3(1, rT_N), 256>>>(x, wt_xp1, b_xp1, t_buf, N, 128, 128, nullptr, nullptr, nullptr);
    // xp = t @ W_xp2 + b_xp2
    hgemm_k<1><<<dim3(3, rT_N), 256>>>(t_buf, wt_xp2, b_xp2, xp_buf, N, 128, 384, nullptr, nullptr, nullptr);
    // p = (edge_feat @ W_ep + b_ep) * xp * INV3  (in place over xp_buf)
    hgemm_k<6><<<dim3(3, rT_N), 256>>>(edge_f, wt_ep, b_ep, xp_buf, N, K_edge, 384, xp_buf, nullptr, nullptr);
    // xn, vecn
    {
        int tot = N * FDIM;
        node_elem_k<<<(tot + 255) / 256, 256>>>(xp_buf, x, vec, edge_ud, xn_buf, ep_buf, N);
    }
    // u = ssilu(xn @ W_sl1[:F] + sB[batch])
    hgemm_k<3><<<dim3(1, rT_N), 256>>>(xn_buf, wt_sl1, nullptr, t_buf, N, 128, 128, sB, nullptr, batch);
    // hx = ssilu(u @ W_sl2 + b_sl2) + xn
    hgemm_k<4><<<dim3(1, rT_N), 256>>>(t_buf, wt_sl2, b_sl2, out + o0, N, 128, 128, xn_buf, nullptr, nullptr);
    // hvec = vecn @ W_vl + vecn + VB[batch]
    hgemm_k<7><<<dim3(1, rT_3N), 256>>>(ep_buf, wt_vl, nullptr, out + o1, 3 * N, 128, 128, ep_buf, VB, batch);

    // ---- segment reduction ----
    {
        int nz = B * 128 + B * 384 + B;
        zero_k<<<(nz + 255) / 256, 256>>>(sum_x, nz);
        counts_k<<<(N + 255) / 256, 256>>>(batch, cnt, N);
        int rpb1 = 256;
        seg_reduce_k<<<(N + rpb1 - 1) / rpb1, 128>>>(out + o0, batch, sum_x, N, 128, rpb1);
        int rpb2 = 128;
        seg_reduce_k<<<(N + rpb2 - 1) / rpb2, 384>>>(out + o1, batch, sum_vec, N, 384, rpb2);
    }

    // ---- global phase (small, tf32 path) ----
    int tB = B * 128;
    g1_k<<<(tB + 255) / 256, 256>>>(sum_x, sum_vec, cnt, scalar_l, vector_l, gcat, Av, B);
    tgemm_k<2><<<dim3(gM_B, 1), 256>>>(gcat, W_sg1, b_sg1, tmp1, B, 256, 128, nullptr, nullptr);
    tgemm_k<2><<<dim3(gM_B, 1), 256>>>(tmp1, W_sg2, b_sg2, stmp, B, 128, 128, nullptr, nullptr);
    tgemm_k<0><<<dim3(gM_3B, 1), 256>>>(Av, W_vg, nullptr, vtmpB, 3 * B, 128, 128, nullptr, nullptr);
    g2_k<<<(tB + 255) / 256, 256>>>(scalar_l, stmp, vector_l, vtmpB, sl, vl, B);
    tgemm_k<0><<<dim3(gM_3B, 2), 256>>>(vl, W_vp, nullptr, hh, 3 * B, 128, 256, nullptr, nullptr);
    g3_k<<<(tB + 255) / 256, 256>>>(hh, sl, cat2, B);
    tgemm_k<2><<<dim3(gM_B, 1), 256>>>(cat2, W_lp1, b_lp1, t2, B, 256, 128, nullptr, nullptr);
    tgemm_k<1><<<dim3(gM_B, 3), 256>>>(t2, W_lp2, b_lp2, sh, B, 128, 384, nullptr, nullptr);
    g4_k<<<(tB + 255) / 256, 256>>>(sh, sl, hh, vl, out + o2, out + o3, B);
    {
        int rows = 3 * B;
        int thr = 256;
        int blks = (rows * 32 + thr - 1) / thr;
        ldelta_k<<<blks, thr>>>(out + o3, W_ml, out + o4, rows);
    }
}

// round 8
// speedup vs baseline: 1.2171x; 1.1185x over previous
#include <cuda_runtime.h>
#include <cuda_fp16.h>
#include <math.h>
#include <stdint.h>

#define FDIM 128
#define SSCALE 1.6666666666666667f   // 1/0.6
#define INV3 0.5773502691896258f     // 1/sqrt(3)
#define INVH 0.08838834764831845f    // 1/sqrt(128)

static __device__ float g_buf[127000000];

__device__ __forceinline__ float ssilu_f(float v) {
    return v * SSCALE / (1.0f + __expf(-v));
}

__device__ __forceinline__ float to_tf32_f(float x) {
    uint32_t r;
    asm("cvt.rna.tf32.f32 %0, %1;" : "=r"(r) : "f"(x));
    return __uint_as_float(r);
}

__device__ __forceinline__ uint32_t pack_h2(float a, float b) {
    __half2 h = __floats2half2_rn(a, b);
    return *reinterpret_cast<uint32_t*>(&h);
}

__device__ __forceinline__ uint32_t smem_to_u32(const void* smem_ptr) {
    uint32_t addr;
    asm("{ .reg .u64 tmp; cvta.to.shared.u64 tmp, %1; cvt.u32.u64 %0, tmp; }"
        : "=r"(addr) : "l"(smem_ptr));
    return addr;
}

__device__ __forceinline__ void ldsm_x4(uint32_t addr, uint32_t* r) {
    asm volatile("ldmatrix.sync.aligned.m8n8.x4.shared.b16 {%0,%1,%2,%3}, [%4];"
        : "=r"(r[0]), "=r"(r[1]), "=r"(r[2]), "=r"(r[3]) : "r"(addr));
}

__device__ __forceinline__ void mma_f16(float* d, const uint32_t* a,
                                        const uint32_t* b, const float* c) {
    asm volatile(
        "mma.sync.aligned.m16n8k16.row.col.f32.f16.f16.f32 "
        "{%0,%1,%2,%3},{%4,%5,%6,%7},{%8,%9},{%10,%11,%12,%13};"
        : "=f"(d[0]), "=f"(d[1]), "=f"(d[2]), "=f"(d[3])
        : "r"(a[0]), "r"(a[1]), "r"(a[2]), "r"(a[3]),
          "r"(b[0]), "r"(b[1]),
          "f"(c[0]), "f"(c[1]), "f"(c[2]), "f"(c[3]));
}

__device__ __forceinline__ void mma_tf32(float* d, const uint32_t* a,
                                         const uint32_t* b, const float* c) {
    asm volatile(
        "mma.sync.aligned.m16n8k8.row.col.f32.tf32.tf32.f32 "
        "{%0,%1,%2,%3},{%4,%5,%6,%7},{%8,%9},{%10,%11,%12,%13};"
        : "=f"(d[0]), "=f"(d[1]), "=f"(d[2]), "=f"(d[3])
        : "r"(a[0]), "r"(a[1]), "r"(a[2]), "r"(a[3]),
          "r"(b[0]), "r"(b[1]),
          "f"(c[0]), "f"(c[1]), "f"(c[2]), "f"(c[3]));
}

// ---------------------------------------------------------------------------
__global__ void wtrans_k(const float* __restrict__ W, float* __restrict__ WT,
                         int K, int Cc)
{
    int id = blockIdx.x * 256 + threadIdx.x;
    if (id >= K * Cc) return;
    int k = id % K;
    int c = id / K;
    WT[id] = W[(size_t)k * Cc + c];
}

// ---------------------------------------------------------------------------
// fp16 ldmatrix GEMM (as validated in R7). WT is transposed weights [Cc,K].
// EPI: 1=+bias 2=ssilu(+bias) 6=(v+bias)*extra[r*Cc+c]*INV3
//      7=v+extra[r*128+c]+extra2[(bidx[r/3]*3+r%3)*128+c]
// ---------------------------------------------------------------------------
template <int EPI>
__global__ void __launch_bounds__(256, 2) hgemm_k(
    const float* __restrict__ A, const float* __restrict__ WT,
    const float* __restrict__ bias, float* __restrict__ C,
    int M, int K, int Cc,
    const float* __restrict__ extra, const float* __restrict__ extra2,
    const int* __restrict__ bidx)
{
    __shared__ uint32_t As[128 * 16];
    __shared__ uint32_t Bs[128 * 16];

    const int tid = threadIdx.x;
    const int warp = tid >> 5;
    const int lane = tid & 31;
    const int wm = warp & 1;
    const int wn = warp >> 1;
    const int g = lane >> 2;
    const int tig = lane & 3;
    const int row0 = blockIdx.y * 128;
    const int col0 = blockIdx.x * 128;

    const uint32_t as_b = smem_to_u32(As);
    const uint32_t bs_b = smem_to_u32(Bs);

    const int l_row = tid >> 2;
    const int l_c = tid & 3;

    const uint32_t a_hi = lane >> 4;
    const uint32_t b_hi = (lane >> 3) & 1;
    uint32_t a_row64[4], a_sw[4];
    #pragma unroll
    for (int mi = 0; mi < 4; mi++) {
        int row = wm * 64 + mi * 16 + (lane & 15);
        a_row64[mi] = as_b + row * 64;
        a_sw[mi] = (row >> 1) & 3;
    }
    uint32_t b_row64[2], b_sw[2];
    #pragma unroll
    for (int p = 0; p < 2; p++) {
        int row = wn * 32 + p * 16 + (lane & 7) + ((lane >> 4) ? 8 : 0);
        b_row64[p] = bs_b + row * 64;
        b_sw[p] = (row >> 1) & 3;
    }

    float acc[4][4][4];
    #pragma unroll
    for (int i = 0; i < 4; i++)
        #pragma unroll
        for (int j = 0; j < 4; j++)
            #pragma unroll
            for (int q = 0; q < 4; q++) acc[i][j][q] = 0.0f;

    for (int k0 = 0; k0 < K; k0 += 32) {
        uint4 av[2], bv[2];
        #pragma unroll
        for (int t = 0; t < 2; t++) {
            int row = l_row + t * 64;
            int ga = row0 + row;
            if (ga >= M) ga = M - 1;
            const float* ap = A + (size_t)ga * K + k0 + l_c * 8;
            float4 a1 = *reinterpret_cast<const float4*>(ap);
            float4 a2 = *reinterpret_cast<const float4*>(ap + 4);
            av[t] = make_uint4(pack_h2(a1.x, a1.y), pack_h2(a1.z, a1.w),
                               pack_h2(a2.x, a2.y), pack_h2(a2.z, a2.w));
            const float* bp = WT + (size_t)(col0 + row) * K + k0 + l_c * 8;
            float4 b1 = *reinterpret_cast<const float4*>(bp);
            float4 b2 = *reinterpret_cast<const float4*>(bp + 4);
            bv[t] = make_uint4(pack_h2(b1.x, b1.y), pack_h2(b1.z, b1.w),
                               pack_h2(b2.x, b2.y), pack_h2(b2.z, b2.w));
        }
        __syncthreads();
        #pragma unroll
        for (int t = 0; t < 2; t++) {
            int row = l_row + t * 64;
            uint32_t off = row * 64 + ((uint32_t)(l_c ^ ((row >> 1) & 3)) << 4);
            *reinterpret_cast<uint4*>((char*)As + off) = av[t];
            *reinterpret_cast<uint4*>((char*)Bs + off) = bv[t];
        }
        __syncthreads();

        #pragma unroll
        for (int s = 0; s < 2; s++) {
            uint32_t afr[4][4];
            #pragma unroll
            for (int mi = 0; mi < 4; mi++)
                ldsm_x4(a_row64[mi] + (((2 * s + a_hi) ^ a_sw[mi]) << 4), afr[mi]);
            uint32_t bfr[2][4];
            #pragma unroll
            for (int p = 0; p < 2; p++)
                ldsm_x4(b_row64[p] + (((2 * s + b_hi) ^ b_sw[p]) << 4), bfr[p]);
            #pragma unroll
            for (int mi = 0; mi < 4; mi++)
                #pragma unroll
                for (int nj = 0; nj < 4; nj++)
                    mma_f16(acc[mi][nj], afr[mi],
                            &bfr[nj >> 1][(nj & 1) * 2], acc[mi][nj]);
        }
    }

    #pragma unroll
    for (int mi = 0; mi < 4; mi++) {
        int rbase = row0 + wm * 64 + mi * 16 + g;
        #pragma unroll
        for (int half = 0; half < 2; half++) {
            int r = rbase + half * 8;
            if (r >= M) continue;
            size_t e2off = 0;
            if (EPI == 7) {
                int nnode = r / 3;
                e2off = ((size_t)bidx[nnode] * 3 + (r - nnode * 3)) * 128;
            }
            #pragma unroll
            for (int nj = 0; nj < 4; nj++) {
                int c = col0 + wn * 32 + nj * 8 + tig * 2;
                #pragma unroll
                for (int e = 0; e < 2; e++) {
                    float v = acc[mi][nj][half * 2 + e];
                    int cc = c + e;
                    if (EPI == 1) v += bias[cc];
                    else if (EPI == 2) v = ssilu_f(v + bias[cc]);
                    else if (EPI == 6) v = (v + bias[cc]) * extra[(size_t)r * Cc + cc] * INV3;
                    else if (EPI == 7) v = v + extra[(size_t)r * 128 + cc] + extra2[e2off + cc];
                    C[(size_t)r * Cc + cc] = v;
                }
            }
        }
    }
}

// ---------------------------------------------------------------------------
// Fused double GEMM: u = ssilu(A@W1 + sB[bidx[r]]); hx = ssilu(u@W2 + b2) + A
// A = xn [M,128]; W1, W2 given transposed [128,128]. One CTA = 128 rows, full
// width. u lives only in smem (fp16, 4 swizzled 32-k slices).
// ---------------------------------------------------------------------------
__global__ void __launch_bounds__(256, 2) hgemm2_k(
    const float* __restrict__ A, const float* __restrict__ WT1,
    const float* __restrict__ WT2,
    const float* __restrict__ sB, const float* __restrict__ bias2,
    const int* __restrict__ bidx, float* __restrict__ C, int M)
{
    __shared__ uint32_t Upool[8192];   // 32KB: stage1 As=slice0, Bs=slice1; then u slices 0..3
    __shared__ uint32_t Bs2[2048];     // 8KB

    uint32_t* As = Upool;
    uint32_t* Bs = Upool + 2048;

    const int tid = threadIdx.x;
    const int warp = tid >> 5;
    const int lane = tid & 31;
    const int wm = warp & 1;
    const int wn = warp >> 1;
    const int g = lane >> 2;
    const int tig = lane & 3;
    const int row0 = blockIdx.y * 128;

    const uint32_t as_b = smem_to_u32(As);
    const uint32_t bs_b = smem_to_u32(Bs);
    const uint32_t u_b  = smem_to_u32(Upool);
    const uint32_t bs2_b = smem_to_u32(Bs2);

    const int l_row = tid >> 2;
    const int l_c = tid & 3;

    const uint32_t a_hi = lane >> 4;
    const uint32_t b_hi = (lane >> 3) & 1;
    uint32_t a_off[4], a_sw[4];
    #pragma unroll
    for (int mi = 0; mi < 4; mi++) {
        int row = wm * 64 + mi * 16 + (lane & 15);
        a_off[mi] = row * 64;
        a_sw[mi] = (row >> 1) & 3;
    }
    uint32_t b_off[2], b_sw[2];
    #pragma unroll
    for (int p = 0; p < 2; p++) {
        int row = wn * 32 + p * 16 + (lane & 7) + ((lane >> 4) ? 8 : 0);
        b_off[p] = row * 64;
        b_sw[p] = (row >> 1) & 3;
    }

    float acc[4][4][4];
    #pragma unroll
    for (int i = 0; i < 4; i++)
        #pragma unroll
        for (int j = 0; j < 4; j++)
            #pragma unroll
            for (int q = 0; q < 4; q++) acc[i][j][q] = 0.0f;

    // ---- stage 1: acc = A @ W1 ----
    for (int k0 = 0; k0 < 128; k0 += 32) {
        uint4 av[2], bv[2];
        #pragma unroll
        for (int t = 0; t < 2; t++) {
            int row = l_row + t * 64;
            int ga = row0 + row;
            if (ga >= M) ga = M - 1;
            const float* ap = A + (size_t)ga * 128 + k0 + l_c * 8;
            float4 a1 = *reinterpret_cast<const float4*>(ap);
            float4 a2 = *reinterpret_cast<const float4*>(ap + 4);
            av[t] = make_uint4(pack_h2(a1.x, a1.y), pack_h2(a1.z, a1.w),
                               pack_h2(a2.x, a2.y), pack_h2(a2.z, a2.w));
            const float* bp = WT1 + (size_t)row * 128 + k0 + l_c * 8;
            float4 b1 = *reinterpret_cast<const float4*>(bp);
            float4 b2 = *reinterpret_cast<const float4*>(bp + 4);
            bv[t] = make_uint4(pack_h2(b1.x, b1.y), pack_h2(b1.z, b1.w),
                               pack_h2(b2.x, b2.y), pack_h2(b2.z, b2.w));
        }
        __syncthreads();
        #pragma unroll
        for (int t = 0; t < 2; t++) {
            int row = l_row + t * 64;
            uint32_t off = row * 64 + ((uint32_t)(l_c ^ ((row >> 1) & 3)) << 4);
            *reinterpret_cast<uint4*>((char*)As + off) = av[t];
            *reinterpret_cast<uint4*>((char*)Bs + off) = bv[t];
        }
        __syncthreads();
        #pragma unroll
        for (int s = 0; s < 2; s++) {
            uint32_t afr[4][4];
            #pragma unroll
            for (int mi = 0; mi < 4; mi++)
                ldsm_x4(as_b + a_off[mi] + (((2 * s + a_hi) ^ a_sw[mi]) << 4), afr[mi]);
            uint32_t bfr[2][4];
            #pragma unroll
            for (int p = 0; p < 2; p++)
                ldsm_x4(bs_b + b_off[p] + (((2 * s + b_hi) ^ b_sw[p]) << 4), bfr[p]);
            #pragma unroll
            for (int mi = 0; mi < 4; mi++)
                #pragma unroll
                for (int nj = 0; nj < 4; nj++)
                    mma_f16(acc[mi][nj], afr[mi],
                            &bfr[nj >> 1][(nj & 1) * 2], acc[mi][nj]);
        }
    }

    // ---- write u = ssilu(acc + sB[bidx[r]]) into Upool as fp16 slices ----
    __syncthreads();
    #pragma unroll
    for (int mi = 0; mi < 4; mi++) {
        int rloc = wm * 64 + mi * 16 + g;
        #pragma unroll
        for (int half = 0; half < 2; half++) {
            int rl = rloc + half * 8;
            int rg = row0 + rl;
            int rr = rg < M ? rg : M - 1;
            int rb = bidx[rr];
            #pragma unroll
            for (int nj = 0; nj < 4; nj++) {
                int c = wn * 32 + nj * 8 + tig * 2;
                float v0 = ssilu_f(acc[mi][nj][half * 2 + 0] + sB[(size_t)rb * 128 + c]);
                float v1 = ssilu_f(acc[mi][nj][half * 2 + 1] + sB[(size_t)rb * 128 + c + 1]);
                uint32_t chunk = (uint32_t)(c & 31) >> 3;
                uint32_t byte = (uint32_t)(c >> 5) * 8192 + rl * 64
                              + ((chunk ^ ((uint32_t)(rl >> 1) & 3)) << 4) + ((c & 7) * 2);
                *reinterpret_cast<uint32_t*>((char*)Upool + byte) = pack_h2(v0, v1);
            }
        }
    }
    __syncthreads();

    // ---- stage 2: acc2 = u @ W2 ----
    float acc2[4][4][4];
    #pragma unroll
    for (int i = 0; i < 4; i++)
        #pragma unroll
        for (int j = 0; j < 4; j++)
            #pragma unroll
            for (int q = 0; q < 4; q++) acc2[i][j][q] = 0.0f;

    for (int s4 = 0; s4 < 4; s4++) {
        uint4 bv[2];
        #pragma unroll
        for (int t = 0; t < 2; t++) {
            int row = l_row + t * 64;
            const float* bp = WT2 + (size_t)row * 128 + s4 * 32 + l_c * 8;
            float4 b1 = *reinterpret_cast<const float4*>(bp);
            float4 b2 = *reinterpret_cast<const float4*>(bp + 4);
            bv[t] = make_uint4(pack_h2(b1.x, b1.y), pack_h2(b1.z, b1.w),
                               pack_h2(b2.x, b2.y), pack_h2(b2.z, b2.w));
        }
        __syncthreads();   // prior ldsm reads of Bs2 done (no-op hazard for s4=0)
        #pragma unroll
        for (int t = 0; t < 2; t++) {
            int row = l_row + t * 64;
            uint32_t off = row * 64 + ((uint32_t)(l_c ^ ((row >> 1) & 3)) << 4);
            *reinterpret_cast<uint4*>((char*)Bs2 + off) = bv[t];
        }
        __syncthreads();
        #pragma unroll
        for (int s = 0; s < 2; s++) {
            uint32_t afr[4][4];
            #pragma unroll
            for (int mi = 0; mi < 4; mi++)
                ldsm_x4(u_b + s4 * 8192 + a_off[mi] + (((2 * s + a_hi) ^ a_sw[mi]) << 4), afr[mi]);
            uint32_t bfr[2][4];
            #pragma unroll
            for (int p = 0; p < 2; p++)
                ldsm_x4(bs2_b + b_off[p] + (((2 * s + b_hi) ^ b_sw[p]) << 4), bfr[p]);
            #pragma unroll
            for (int mi = 0; mi < 4; mi++)
                #pragma unroll
                for (int nj = 0; nj < 4; nj++)
                    mma_f16(acc2[mi][nj], afr[mi],
                            &bfr[nj >> 1][(nj & 1) * 2], acc2[mi][nj]);
        }
    }

    // ---- epilogue: hx = ssilu(acc2 + b2) + xn ----
    #pragma unroll
    for (int mi = 0; mi < 4; mi++) {
        int rbase = row0 + wm * 64 + mi * 16 + g;
        #pragma unroll
        for (int half = 0; half < 2; half++) {
            int r = rbase + half * 8;
            if (r >= M) continue;
            #pragma unroll
            for (int nj = 0; nj < 4; nj++) {
                int c = wn * 32 + nj * 8 + tig * 2;
                #pragma unroll
                for (int e = 0; e < 2; e++) {
                    int cc = c + e;
                    float v = ssilu_f(acc2[mi][nj][half * 2 + e] + bias2[cc])
                            + A[(size_t)r * 128 + cc];
                    C[(size_t)r * 128 + cc] = v;
                }
            }
        }
    }
}

// ---------------------------------------------------------------------------
// mma.sync tf32 GEMM for small B-scale matrices (VB, sB only)
// ---------------------------------------------------------------------------
template <int EPI>
__global__ void __launch_bounds__(256) tgemm_k(
    const float* __restrict__ A, const float* __restrict__ W,
    const float* __restrict__ bias, float* __restrict__ C,
    int M, int K, int Cc)
{
    __shared__ float As[16][136];
    __shared__ float Ws[16][136];

    const int tid = threadIdx.x;
    const int row0 = blockIdx.x * 128;
    const int col0 = blockIdx.y * 128;
    const int warp = tid >> 5;
    const int lane = tid & 31;
    const int wm = warp & 1;
    const int wn = warp >> 1;
    const int g = lane >> 2;
    const int tig = lane & 3;

    float acc[4][4][4];
    #pragma unroll
    for (int i = 0; i < 4; i++)
        #pragma unroll
        for (int j = 0; j < 4; j++)
            #pragma unroll
            for (int q = 0; q < 4; q++) acc[i][j][q] = 0.0f;

    for (int k0 = 0; k0 < K; k0 += 16) {
        #pragma unroll
        for (int t = 0; t < 2; t++) {
            int id = tid + t * 256;
            int row = id >> 2;
            int kc = (id & 3) * 4;
            float4 av;
            int grow = row0 + row;
            if (grow < M)
                av = *reinterpret_cast<const float4*>(A + (size_t)grow * K + k0 + kc);
            else
                av = make_float4(0.f, 0.f, 0.f, 0.f);
            As[kc + 0][row] = to_tf32_f(av.x);
            As[kc + 1][row] = to_tf32_f(av.y);
            As[kc + 2][row] = to_tf32_f(av.z);
            As[kc + 3][row] = to_tf32_f(av.w);
        }
        #pragma unroll
        for (int t = 0; t < 2; t++) {
            int id = tid + t * 256;
            int kr = id >> 5;
            int c4 = (id & 31) * 4;
            float4 wv = *reinterpret_cast<const float4*>(
                W + (size_t)(k0 + kr) * Cc + col0 + c4);
            Ws[kr][c4 + 0] = to_tf32_f(wv.x);
            Ws[kr][c4 + 1] = to_tf32_f(wv.y);
            Ws[kr][c4 + 2] = to_tf32_f(wv.z);
            Ws[kr][c4 + 3] = to_tf32_f(wv.w);
        }
        __syncthreads();

        #pragma unroll
        for (int s = 0; s < 2; s++) {
            const int kb = s * 8;
            uint32_t afr[4][4];
            uint32_t bfr[4][2];
            #pragma unroll
            for (int mi = 0; mi < 4; mi++) {
                int mr = wm * 64 + mi * 16 + g;
                afr[mi][0] = __float_as_uint(As[kb + tig][mr]);
                afr[mi][1] = __float_as_uint(As[kb + tig][mr + 8]);
                afr[mi][2] = __float_as_uint(As[kb + tig + 4][mr]);
                afr[mi][3] = __float_as_uint(As[kb + tig + 4][mr + 8]);
            }
            #pragma unroll
            for (int nj = 0; nj < 4; nj++) {
                int nc = wn * 32 + nj * 8 + g;
                bfr[nj][0] = __float_as_uint(Ws[kb + tig][nc]);
                bfr[nj][1] = __float_as_uint(Ws[kb + tig + 4][nc]);
            }
            #pragma unroll
            for (int mi = 0; mi < 4; mi++)
                #pragma unroll
                for (int nj = 0; nj < 4; nj++)
                    mma_tf32(acc[mi][nj], afr[mi], bfr[nj], acc[mi][nj]);
        }
        __syncthreads();
    }

    #pragma unroll
    for (int mi = 0; mi < 4; mi++) {
        int rbase = row0 + wm * 64 + mi * 16 + g;
        #pragma unroll
        for (int half = 0; half < 2; half++) {
            int r = rbase + half * 8;
            if (r >= M) continue;
            #pragma unroll
            for (int nj = 0; nj < 4; nj++) {
                int c = col0 + wn * 32 + nj * 8 + tig * 2;
                #pragma unroll
                for (int e = 0; e < 2; e++) {
                    float v = acc[mi][nj][half * 2 + e];
                    int cc = c + e;
                    if (EPI == 1) v += bias[cc];
                    C[(size_t)r * Cc + cc] = v;
                }
            }
        }
    }
}

// ---------------------------------------------------------------------------
__global__ void node_elem_k(
    const float* p, const float* x,
    const float* vec, const float* ud,
    float* xn, float* vecn, int N)
{
    int idx = blockIdx.x * blockDim.x + threadIdx.x;
    if (idx >= N * FDIM) return;
    int n = idx >> 7;
    int f = idx & 127;
    size_t b3 = (size_t)n * 384;

    float p1 = p[b3 + f], p2 = p[b3 + 128 + f], p3 = p[b3 + 256 + f];

    xn[(size_t)n * 128 + f] = p3 + x[(size_t)n * 128 + f];

    float u0 = ud[n * 3 + 0], u1 = ud[n * 3 + 1], u2 = ud[n * 3 + 2];
    float v0 = vec[b3 + 0 * 128 + f];
    float v1 = vec[b3 + 1 * 128 + f];
    float v2 = vec[b3 + 2 * 128 + f];

    vecn[b3 + 0 * 128 + f] = (p1 * v0 + p2 * u0) * INVH;
    vecn[b3 + 1 * 128 + f] = (p1 * v1 + p2 * u1) * INVH;
    vecn[b3 + 2 * 128 + f] = (p1 * v2 + p2 * u2) * INVH;
}

__global__ void zero_k(float* p, int n) {
    int i = blockIdx.x * blockDim.x + threadIdx.x;
    if (i < n) p[i] = 0.0f;
}

// Sorted-segment sum + run-length counts (Cc=128 variant)
__global__ void seg_reduce_cnt_k(const float* src, const int* batch, float* dst,
                                 float* cnt, int N, int rows_per_blk)
{
    int c = threadIdx.x;
    int r0 = blockIdx.x * rows_per_blk;
    if (r0 >= N) return;
    int r1 = min(r0 + rows_per_blk, N);
    int cur = batch[r0];
    float s = 0.0f;
    int runlen = 0;
    for (int r = r0; r < r1; r++) {
        int b = batch[r];
        if (b != cur) {
            atomicAdd(&dst[(size_t)cur * 128 + c], s);
            if (c == 0) atomicAdd(&cnt[cur], (float)runlen);
            s = 0.0f;
            runlen = 0;
            cur = b;
        }
        s += src[(size_t)r * 128 + c];
        runlen++;
    }
    atomicAdd(&dst[(size_t)cur * 128 + c], s);
    if (c == 0) atomicAdd(&cnt[cur], (float)runlen);
}

__global__ void seg_reduce_k(const float* src, const int* batch, float* dst,
                             int N, int Cc, int rows_per_blk)
{
    int c = threadIdx.x;
    int r0 = blockIdx.x * rows_per_blk;
    if (r0 >= N) return;
    int r1 = min(r0 + rows_per_blk, N);
    int cur = batch[r0];
    float s = 0.0f;
    for (int r = r0; r < r1; r++) {
        int b = batch[r];
        if (b != cur) {
            atomicAdd(&dst[(size_t)cur * Cc + c], s);
            s = 0.0f;
            cur = b;
        }
        s += src[(size_t)r * Cc + c];
    }
    atomicAdd(&dst[(size_t)cur * Cc + c], s);
}

// ---------------------------------------------------------------------------
// Fused global phase: one CTA per batch row b (128 threads).
// Replaces g1, sg1, sg2, vg, g2, vp, g3, lp1, lp2, g4, ldelta.
// ---------------------------------------------------------------------------
__global__ void __launch_bounds__(128) global_k(
    const float* __restrict__ sum_x, const float* __restrict__ sum_vec,
    const float* __restrict__ cnt,
    const float* __restrict__ scalar_l, const float* __restrict__ vector_l,
    const float* __restrict__ W_sg1, const float* __restrict__ b_sg1,
    const float* __restrict__ W_sg2, const float* __restrict__ b_sg2,
    const float* __restrict__ W_vg, const float* __restrict__ W_vp,
    const float* __restrict__ W_lp1, const float* __restrict__ b_lp1,
    const float* __restrict__ W_lp2, const float* __restrict__ b_lp2,
    const float* __restrict__ W_ml,
    float* __restrict__ out_sl, float* __restrict__ out_vl,
    float* __restrict__ out_ld)
{
    int b = blockIdx.x;
    int f = threadIdx.x;
    __shared__ float s_g[256];
    __shared__ float s_t[128];
    __shared__ float s_av[3][128];
    __shared__ float s_vl[3][128];
    __shared__ float s_h1[3][128];
    __shared__ float s_red[12];

    float invc = 1.0f / fmaxf(cnt[b], 1.0f);
    size_t bf = (size_t)b * 128 + f;
    float sclf = scalar_l[bf];
    s_g[f] = sum_x[bf] * invc;
    s_g[128 + f] = sclf;
    float vlg[3];
    #pragma unroll
    for (int d = 0; d < 3; d++) {
        size_t o = (size_t)b * 384 + d * 128 + f;
        vlg[d] = vector_l[o];
        s_av[d][f] = sum_vec[o] * invc + vlg[d];
    }
    __syncthreads();

    // tmp1 = ssilu(g @ W_sg1 + b_sg1)
    float acc = b_sg1[f];
    #pragma unroll 8
    for (int k = 0; k < 256; k++) acc += s_g[k] * W_sg1[k * 128 + f];
    s_t[f] = ssilu_f(acc);
    __syncthreads();

    // sl = scalar_l + ssilu(tmp1 @ W_sg2 + b_sg2)
    acc = b_sg2[f];
    #pragma unroll 8
    for (int k = 0; k < 128; k++) acc += s_t[k] * W_sg2[k * 128 + f];
    float sl = sclf + ssilu_f(acc);

    // vl_d = vector_l + Av_d @ W_vg
    float vl[3];
    #pragma unroll
    for (int d = 0; d < 3; d++) {
        float a = 0.0f;
        #pragma unroll 8
        for (int k = 0; k < 128; k++) a += s_av[d][k] * W_vg[k * 128 + f];
        vl[d] = vlg[d] + a;
        s_vl[d][f] = vl[d];
    }
    __syncthreads();

    // hh = vl @ W_vp ; h1 = cols[0:128), h2 = cols[128:256)
    float vn = 1e-8f;
    #pragma unroll
    for (int d = 0; d < 3; d++) {
        float h1 = 0.0f, h2 = 0.0f;
        #pragma unroll 8
        for (int k = 0; k < 128; k++) {
            float t = s_vl[d][k];
            h1 += t * W_vp[k * 256 + f];
            h2 += t * W_vp[k * 256 + 128 + f];
        }
        s_h1[d][f] = h1;
        vn += h2 * h2;
    }
    s_g[f] = sl;
    s_g[128 + f] = sqrtf(vn);
    __syncthreads();

    // t2 = ssilu(cat2 @ W_lp1 + b_lp1)
    acc = b_lp1[f];
    #pragma unroll 8
    for (int k = 0; k < 256; k++) acc += s_g[k] * W_lp1[k * 128 + f];
    s_t[f] = ssilu_f(acc);
    __syncthreads();

    // sh = t2 @ W_lp2 + b_lp2 -> s1, s2, s3
    float s1 = b_lp2[f], s2 = b_lp2[128 + f], s3 = b_lp2[256 + f];
    #pragma unroll 4
    for (int k = 0; k < 128; k++) {
        float t = s_t[k];
        s1 += t * W_lp2[k * 384 + f];
        s2 += t * W_lp2[k * 384 + 128 + f];
        s3 += t * W_lp2[k * 384 + 256 + f];
    }
    out_sl[bf] = s2 + sl * tanhf(s3);

    float wml = W_ml[f];
    float part[3];
    #pragma unroll
    for (int d = 0; d < 3; d++) {
        float v = s1 * s_h1[d][f] + vl[d];
        out_vl[(size_t)b * 384 + d * 128 + f] = v;
        part[d] = v * wml;
    }
    #pragma unroll
    for (int d = 0; d < 3; d++)
        #pragma unroll
        for (int o = 16; o; o >>= 1)
            part[d] += __shfl_down_sync(0xffffffff, part[d], o);
    int w = f >> 5, ln = f & 31;
    if (ln == 0) {
        #pragma unroll
        for (int d = 0; d < 3; d++) s_red[d * 4 + w] = part[d];
    }
    __syncthreads();
    if (f < 3)
        out_ld[b * 3 + f] = s_red[f * 4] + s_red[f * 4 + 1]
                          + s_red[f * 4 + 2] + s_red[f * 4 + 3];
}

// ---------------------------------------------------------------------------
extern "C" void kernel_launch(void* const* d_in, const int* in_sizes, int n_in,
                              void* d_out, int out_size)
{
    const float* x        = (const float*)d_in[0];
    const float* scalar_l = (const float*)d_in[1];
    const float* vec      = (const float*)d_in[2];
    const float* vector_l = (const float*)d_in[3];
    const float* edge_f   = (const float*)d_in[4];
    const float* edge_ud  = (const float*)d_in[5];
    const int*   batch    = (const int*)d_in[6];
    const float* W_sg1 = (const float*)d_in[7];  const float* b_sg1 = (const float*)d_in[8];
    const float* W_sg2 = (const float*)d_in[9];  const float* b_sg2 = (const float*)d_in[10];
    const float* W_sl1 = (const float*)d_in[11]; const float* b_sl1 = (const float*)d_in[12];
    const float* W_sl2 = (const float*)d_in[13]; const float* b_sl2 = (const float*)d_in[14];
    const float* W_vg  = (const float*)d_in[15];
    const float* W_vl  = (const float*)d_in[16];
    const float* W_xp1 = (const float*)d_in[17]; const float* b_xp1 = (const float*)d_in[18];
    const float* W_xp2 = (const float*)d_in[19]; const float* b_xp2 = (const float*)d_in[20];
    const float* W_ep  = (const float*)d_in[21]; const float* b_ep  = (const float*)d_in[22];
    const float* W_vp  = (const float*)d_in[23];
    const float* W_lp1 = (const float*)d_in[24]; const float* b_lp1 = (const float*)d_in[25];
    const float* W_lp2 = (const float*)d_in[26]; const float* b_lp2 = (const float*)d_in[27];
    const float* W_ml  = (const float*)d_in[28];

    const int N = in_sizes[0] / FDIM;
    const int B = in_sizes[1] / FDIM;
    const int K_edge = in_sizes[4] / N;   // 64

    float* base = nullptr;
    cudaGetSymbolAddress((void**)&base, g_buf);

    const size_t NF = (size_t)N * FDIM;
    float* t_buf  = base;                 // [N,F]
    float* xp_buf = base + NF;            // [N,3F]  xp -> p
    float* ep_buf = base + 4 * NF;        // [N,3F]  vecn
    float* xn_buf = base + 7 * NF;        // [N,F]
    float* sm     = base + 8 * NF;
    float* sB      = sm;                       // B*128
    float* sum_x   = sm + 65536;               // B*128
    float* sum_vec = sm + 131072;              // B*384
    float* cnt     = sm + 327680;              // B
    float* VB      = sm + 328192;              // 3B*128
    float* wt_xp1  = sm + 524800;              // 128*128
    float* wt_xp2  = sm + 541184;              // 384*128
    float* wt_ep   = sm + 590336;              // 384*64
    float* wt_sl1  = sm + 614912;              // 128*128
    float* wt_sl2  = sm + 631296;              // 128*128
    float* wt_vl   = sm + 647680;              // 128*128

    float* out = (float*)d_out;
    const size_t o0 = 0;
    const size_t o1 = NF;
    const size_t o2 = o1 + 3 * NF;
    const size_t o3 = o2 + (size_t)B * 128;
    const size_t o4 = o3 + (size_t)B * 384;

    const int rT_N  = (N + 127) / 128;
    const int rT_3N = (3 * N + 127) / 128;
    const int gM_B  = (B + 127) / 128;
    const int gM_3B = (3 * B + 127) / 128;

    // launches 0-4: transposes needed early (profiler lands on idx 5 = big GEMM)
    wtrans_k<<<(128 * 128 + 255) / 256, 256>>>(W_xp1, wt_xp1, 128, 128);      // 0
    wtrans_k<<<(128 * 384 + 255) / 256, 256>>>(W_xp2, wt_xp2, 128, 384);      // 1
    wtrans_k<<<(K_edge * 384 + 255) / 256, 256>>>(W_ep, wt_ep, K_edge, 384);  // 2
    wtrans_k<<<(128 * 128 + 255) / 256, 256>>>(W_sl1, wt_sl1, 128, 128);      // 3
    wtrans_k<<<(128 * 128 + 255) / 256, 256>>>(W_sl2, wt_sl2, 128, 128);      // 4

    // 5 (PROFILED): t = ssilu(x @ W_xp1 + b_xp1)
    hgemm_k<2><<<dim3(1, rT_N), 256>>>(x, wt_xp1, b_xp1, t_buf, N, 128, 128, nullptr, nullptr, nullptr);

    wtrans_k<<<(128 * 128 + 255) / 256, 256>>>(W_vl, wt_vl, 128, 128);        // 6
    // VB = vector_l @ W_vl
    tgemm_k<0><<<dim3(gM_3B, 1), 256>>>(vector_l, W_vl, nullptr, VB, 3 * B, 128, 128);  // 7
    // sB = scalar_l @ W_sl1[F:] + b_sl1
    tgemm_k<1><<<dim3(gM_B, 1), 256>>>(scalar_l, W_sl1 + 128 * 128, b_sl1, sB, B, 128, 128);  // 8

    // xp = t @ W_xp2 + b_xp2
    hgemm_k<1><<<dim3(3, rT_N), 256>>>(t_buf, wt_xp2, b_xp2, xp_buf, N, 128, 384, nullptr, nullptr, nullptr);  // 9
    // p = (edge_feat @ W_ep + b_ep) * xp * INV3  (in place)
    hgemm_k<6><<<dim3(3, rT_N), 256>>>(edge_f, wt_ep, b_ep, xp_buf, N, K_edge, 384, xp_buf, nullptr, nullptr); // 10
    // xn, vecn
    node_elem_k<<<(N * FDIM + 255) / 256, 256>>>(xp_buf, x, vec, edge_ud, xn_buf, ep_buf, N);  // 11
    // hx = ssilu(ssilu(xn@W_sl1 + sB[batch]) @ W_sl2 + b_sl2) + xn   (fused)
    hgemm2_k<<<dim3(1, rT_N), 256>>>(xn_buf, wt_sl1, wt_sl2, sB, b_sl2, batch, out + o0, N);   // 12
    // hvec = vecn @ W_vl + vecn + VB[batch]
    hgemm_k<7><<<dim3(1, rT_3N), 256>>>(ep_buf, wt_vl, nullptr, out + o1, 3 * N, 128, 128, ep_buf, VB, batch); // 13

    // segment reduction (+counts)
    {
        int nz = B * 128 + B * 384 + B;
        zero_k<<<(nz + 255) / 256, 256>>>(sum_x, nz);                          // 14
        seg_reduce_cnt_k<<<(N + 127) / 128, 128>>>(out + o0, batch, sum_x, cnt, N, 128);  // 15
        seg_reduce_k<<<(N + 63) / 64, 384>>>(out + o1, batch, sum_vec, N, 384, 64);       // 16
    }

    // fused global phase
    global_k<<<B, 128>>>(sum_x, sum_vec, cnt, scalar_l, vector_l,
                         W_sg1, b_sg1, W_sg2, b_sg2, W_vg, W_vp,
                         W_lp1, b_lp1, W_lp2, b_lp2, W_ml,
                         out + o2, out + o3, out + o4);                        // 17
}

// round 9
// speedup vs baseline: 1.3918x; 1.1435x over previous
#include <cuda_runtime.h>
#include <cuda_fp16.h>
#include <math.h>
#include <stdint.h>

#define FDIM 128
#define SSCALE 1.6666666666666667f   // 1/0.6
#define INV3 0.5773502691896258f     // 1/sqrt(3)
#define INVH 0.08838834764831845f    // 1/sqrt(128)

static __device__ float g_buf[127000000];

__device__ __forceinline__ float ssilu_f(float v) {
    return v * SSCALE / (1.0f + __expf(-v));
}

__device__ __forceinline__ float to_tf32_f(float x) {
    uint32_t r;
    asm("cvt.rna.tf32.f32 %0, %1;" : "=r"(r) : "f"(x));
    return __uint_as_float(r);
}

__device__ __forceinline__ uint32_t pack_h2(float a, float b) {
    __half2 h = __floats2half2_rn(a, b);
    return *reinterpret_cast<uint32_t*>(&h);
}

__device__ __forceinline__ uint32_t smem_to_u32(const void* smem_ptr) {
    uint32_t addr;
    asm("{ .reg .u64 tmp; cvta.to.shared.u64 tmp, %1; cvt.u32.u64 %0, tmp; }"
        : "=r"(addr) : "l"(smem_ptr));
    return addr;
}

__device__ __forceinline__ void ldsm_x4(uint32_t addr, uint32_t* r) {
    asm volatile("ldmatrix.sync.aligned.m8n8.x4.shared.b16 {%0,%1,%2,%3}, [%4];"
        : "=r"(r[0]), "=r"(r[1]), "=r"(r[2]), "=r"(r[3]) : "r"(addr));
}

__device__ __forceinline__ void mma_f16(float* d, const uint32_t* a,
                                        const uint32_t* b, const float* c) {
    asm volatile(
        "mma.sync.aligned.m16n8k16.row.col.f32.f16.f16.f32 "
        "{%0,%1,%2,%3},{%4,%5,%6,%7},{%8,%9},{%10,%11,%12,%13};"
        : "=f"(d[0]), "=f"(d[1]), "=f"(d[2]), "=f"(d[3])
        : "r"(a[0]), "r"(a[1]), "r"(a[2]), "r"(a[3]),
          "r"(b[0]), "r"(b[1]),
          "f"(c[0]), "f"(c[1]), "f"(c[2]), "f"(c[3]));
}

__device__ __forceinline__ void mma_tf32(float* d, const uint32_t* a,
                                         const uint32_t* b, const float* c) {
    asm volatile(
        "mma.sync.aligned.m16n8k8.row.col.f32.tf32.tf32.f32 "
        "{%0,%1,%2,%3},{%4,%5,%6,%7},{%8,%9},{%10,%11,%12,%13};"
        : "=f"(d[0]), "=f"(d[1]), "=f"(d[2]), "=f"(d[3])
        : "r"(a[0]), "r"(a[1]), "r"(a[2]), "r"(a[3]),
          "r"(b[0]), "r"(b[1]),
          "f"(c[0]), "f"(c[1]), "f"(c[2]), "f"(c[3]));
}

// ---------------------------------------------------------------------------
// All weight transposes + fp16 conversion in ONE launch.
// Segment layout in dst (halves): xp1 | xp2 | ep | sl1 | sl2 | vl
// ---------------------------------------------------------------------------
__global__ void wtrans_all_k(const float* __restrict__ Wxp1, const float* __restrict__ Wxp2,
                             const float* __restrict__ Wep,  const float* __restrict__ Wsl1,
                             const float* __restrict__ Wsl2, const float* __restrict__ Wvl,
                             __half* __restrict__ dst, int ke)
{
    int id = blockIdx.x * 256 + threadIdx.x;
    int s0 = 16384, s1 = 49152, s2 = 384 * ke, s3 = 16384, s4 = 16384, s5 = 16384;
    const float* W; int K, Cc, off, base;
    if (id < s0) { W = Wxp1; K = 128; Cc = 128; base = 0; off = id; }
    else if (id < s0 + s1) { W = Wxp2; K = 128; Cc = 384; base = s0; off = id - s0; }
    else if (id < s0 + s1 + s2) { W = Wep; K = ke; Cc = 384; base = s0 + s1; off = id - s0 - s1; }
    else if (id < s0 + s1 + s2 + s3) { W = Wsl1; K = 128; Cc = 128; base = s0 + s1 + s2; off = id - s0 - s1 - s2; }
    else if (id < s0 + s1 + s2 + s3 + s4) { W = Wsl2; K = 128; Cc = 128; base = s0 + s1 + s2 + s3; off = id - s0 - s1 - s2 - s3; }
    else if (id < s0 + s1 + s2 + s3 + s4 + s5) { W = Wvl; K = 128; Cc = 128; base = s0 + s1 + s2 + s3 + s4; off = id - s0 - s1 - s2 - s3 - s4; }
    else return;
    int k = off % K, c = off / K;
    dst[base + off] = __float2half(W[(size_t)k * Cc + c]);
}

// fp32 -> fp16 bulk convert (n % 8 == 0)
__global__ void f2h_k(const float* __restrict__ src, __half* __restrict__ dst, int n)
{
    int i = (blockIdx.x * 256 + threadIdx.x) * 8;
    if (i >= n) return;
    float4 a = *reinterpret_cast<const float4*>(src + i);
    float4 b = *reinterpret_cast<const float4*>(src + i + 4);
    uint4 o = make_uint4(pack_h2(a.x, a.y), pack_h2(a.z, a.w),
                         pack_h2(b.x, b.y), pack_h2(b.z, b.w));
    *reinterpret_cast<uint4*>(dst + i) = o;
}

// ---------------------------------------------------------------------------
// fp16-native ldmatrix GEMM. A [M,K] half, WT [Cc,K] half. Same smem geometry
// as R7 (64B rows, 16B-chunk XOR swizzle). No conversions in mainloop.
// EPI: 2 = ssilu(v+bias) -> HALF out
//      7 = v + (float)extrah[r*128+c] + extra2[(bidx[r/3]*3+r%3)*128+c] -> float out
// ---------------------------------------------------------------------------
template <int EPI>
__global__ void __launch_bounds__(256, 2) hgemmh_k(
    const __half* __restrict__ A, const __half* __restrict__ WT,
    const float* __restrict__ bias, void* __restrict__ Cout,
    int M, int K, int Cc,
    const __half* __restrict__ extrah, const float* __restrict__ extra2,
    const int* __restrict__ bidx)
{
    __shared__ uint32_t As[128 * 16];
    __shared__ uint32_t Bs[128 * 16];

    const int tid = threadIdx.x;
    const int warp = tid >> 5;
    const int lane = tid & 31;
    const int wm = warp & 1;
    const int wn = warp >> 1;
    const int g = lane >> 2;
    const int tig = lane & 3;
    const int row0 = blockIdx.y * 128;
    const int col0 = blockIdx.x * 128;

    const uint32_t as_b = smem_to_u32(As);
    const uint32_t bs_b = smem_to_u32(Bs);

    const int l_row = tid >> 2;
    const int l_c = tid & 3;

    const uint32_t a_hi = lane >> 4;
    const uint32_t b_hi = (lane >> 3) & 1;
    uint32_t a_row64[4], a_sw[4];
    #pragma unroll
    for (int mi = 0; mi < 4; mi++) {
        int row = wm * 64 + mi * 16 + (lane & 15);
        a_row64[mi] = as_b + row * 64;
        a_sw[mi] = (row >> 1) & 3;
    }
    uint32_t b_row64[2], b_sw[2];
    #pragma unroll
    for (int p = 0; p < 2; p++) {
        int row = wn * 32 + p * 16 + (lane & 7) + ((lane >> 4) ? 8 : 0);
        b_row64[p] = bs_b + row * 64;
        b_sw[p] = (row >> 1) & 3;
    }

    float acc[4][4][4];
    #pragma unroll
    for (int i = 0; i < 4; i++)
        #pragma unroll
        for (int j = 0; j < 4; j++)
            #pragma unroll
            for (int q = 0; q < 4; q++) acc[i][j][q] = 0.0f;

    for (int k0 = 0; k0 < K; k0 += 32) {
        uint4 av[2], bv[2];
        #pragma unroll
        for (int t = 0; t < 2; t++) {
            int row = l_row + t * 64;
            int ga = row0 + row;
            if (ga >= M) ga = M - 1;
            av[t] = *(reinterpret_cast<const uint4*>(A + (size_t)ga * K + k0) + l_c);
            bv[t] = *(reinterpret_cast<const uint4*>(WT + (size_t)(col0 + row) * K + k0) + l_c);
        }
        __syncthreads();
        #pragma unroll
        for (int t = 0; t < 2; t++) {
            int row = l_row + t * 64;
            uint32_t off = row * 64 + ((uint32_t)(l_c ^ ((row >> 1) & 3)) << 4);
            *reinterpret_cast<uint4*>((char*)As + off) = av[t];
            *reinterpret_cast<uint4*>((char*)Bs + off) = bv[t];
        }
        __syncthreads();

        #pragma unroll
        for (int s = 0; s < 2; s++) {
            uint32_t afr[4][4];
            #pragma unroll
            for (int mi = 0; mi < 4; mi++)
                ldsm_x4(a_row64[mi] + (((2 * s + a_hi) ^ a_sw[mi]) << 4), afr[mi]);
            uint32_t bfr[2][4];
            #pragma unroll
            for (int p = 0; p < 2; p++)
                ldsm_x4(b_row64[p] + (((2 * s + b_hi) ^ b_sw[p]) << 4), bfr[p]);
            #pragma unroll
            for (int mi = 0; mi < 4; mi++)
                #pragma unroll
                for (int nj = 0; nj < 4; nj++)
                    mma_f16(acc[mi][nj], afr[mi],
                            &bfr[nj >> 1][(nj & 1) * 2], acc[mi][nj]);
        }
    }

    #pragma unroll
    for (int mi = 0; mi < 4; mi++) {
        int rbase = row0 + wm * 64 + mi * 16 + g;
        #pragma unroll
        for (int half = 0; half < 2; half++) {
            int r = rbase + half * 8;
            if (r >= M) continue;
            size_t e2off = 0;
            if (EPI == 7) {
                int nnode = r / 3;
                e2off = ((size_t)bidx[nnode] * 3 + (r - nnode * 3)) * 128;
            }
            #pragma unroll
            for (int nj = 0; nj < 4; nj++) {
                int c = col0 + wn * 32 + nj * 8 + tig * 2;
                float v0 = acc[mi][nj][half * 2 + 0];
                float v1 = acc[mi][nj][half * 2 + 1];
                if (EPI == 2) {
                    v0 = ssilu_f(v0 + bias[c]);
                    v1 = ssilu_f(v1 + bias[c + 1]);
                    __half* Ch = (__half*)Cout;
                    *reinterpret_cast<uint32_t*>(Ch + (size_t)r * Cc + c) = pack_h2(v0, v1);
                } else if (EPI == 7) {
                    uint32_t eh = *reinterpret_cast<const uint32_t*>(extrah + (size_t)r * 128 + c);
                    __half2 h2 = *reinterpret_cast<__half2*>(&eh);
                    v0 += __low2float(h2) + extra2[e2off + c];
                    v1 += __high2float(h2) + extra2[e2off + c + 1];
                    float* Cf = (float*)Cout;
                    Cf[(size_t)r * Cc + c] = v0;
                    Cf[(size_t)r * Cc + c + 1] = v1;
                }
            }
        }
    }
}

// ---------------------------------------------------------------------------
// Fused product GEMM: p[:, col0:col0+128] =
//   (Th @ Wxp2_slab + bxp2) * (Eh @ Wep_slab + bep) * INV3
// Th [M,128] half, Eh [M,ke] half. grid (3, rowtiles).
// ---------------------------------------------------------------------------
__global__ void __launch_bounds__(256) pgemm_k(
    const __half* __restrict__ Th, const __half* __restrict__ Eh,
    const __half* __restrict__ WTxp2, const __half* __restrict__ WTep,
    const float* __restrict__ bxp2, const float* __restrict__ bep,
    float* __restrict__ P, int M, int ke)
{
    __shared__ uint32_t As[128 * 16];
    __shared__ uint32_t Bs[128 * 16];

    const int tid = threadIdx.x;
    const int warp = tid >> 5;
    const int lane = tid & 31;
    const int wm = warp & 1;
    const int wn = warp >> 1;
    const int g = lane >> 2;
    const int tig = lane & 3;
    const int row0 = blockIdx.y * 128;
    const int col0 = blockIdx.x * 128;   // 0, 128, 256

    const uint32_t as_b = smem_to_u32(As);
    const uint32_t bs_b = smem_to_u32(Bs);

    const int l_row = tid >> 2;
    const int l_c = tid & 3;

    const uint32_t a_hi = lane >> 4;
    const uint32_t b_hi = (lane >> 3) & 1;
    uint32_t a_row64[4], a_sw[4];
    #pragma unroll
    for (int mi = 0; mi < 4; mi++) {
        int row = wm * 64 + mi * 16 + (lane & 15);
        a_row64[mi] = as_b + row * 64;
        a_sw[mi] = (row >> 1) & 3;
    }
    uint32_t b_row64[2], b_sw[2];
    #pragma unroll
    for (int p = 0; p < 2; p++) {
        int row = wn * 32 + p * 16 + (lane & 7) + ((lane >> 4) ? 8 : 0);
        b_row64[p] = bs_b + row * 64;
        b_sw[p] = (row >> 1) & 3;
    }

    float acc1[4][4][4], acc2[4][4][4];
    #pragma unroll
    for (int i = 0; i < 4; i++)
        #pragma unroll
        for (int j = 0; j < 4; j++)
            #pragma unroll
            for (int q = 0; q < 4; q++) { acc1[i][j][q] = 0.0f; acc2[i][j][q] = 0.0f; }

    // ---- GEMM1: Th @ WTxp2 slab (K=128) ----
    for (int k0 = 0; k0 < 128; k0 += 32) {
        uint4 av[2], bv[2];
        #pragma unroll
        for (int t = 0; t < 2; t++) {
            int row = l_row + t * 64;
            int ga = row0 + row;
            if (ga >= M) ga = M - 1;
            av[t] = *(reinterpret_cast<const uint4*>(Th + (size_t)ga * 128 + k0) + l_c);
            bv[t] = *(reinterpret_cast<const uint4*>(WTxp2 + (size_t)(col0 + row) * 128 + k0) + l_c);
        }
        __syncthreads();
        #pragma unroll
        for (int t = 0; t < 2; t++) {
            int row = l_row + t * 64;
            uint32_t off = row * 64 + ((uint32_t)(l_c ^ ((row >> 1) & 3)) << 4);
            *reinterpret_cast<uint4*>((char*)As + off) = av[t];
            *reinterpret_cast<uint4*>((char*)Bs + off) = bv[t];
        }
        __syncthreads();
        #pragma unroll
        for (int s = 0; s < 2; s++) {
            uint32_t afr[4][4];
            #pragma unroll
            for (int mi = 0; mi < 4; mi++)
                ldsm_x4(a_row64[mi] + (((2 * s + a_hi) ^ a_sw[mi]) << 4), afr[mi]);
            uint32_t bfr[2][4];
            #pragma unroll
            for (int p = 0; p < 2; p++)
                ldsm_x4(b_row64[p] + (((2 * s + b_hi) ^ b_sw[p]) << 4), bfr[p]);
            #pragma unroll
            for (int mi = 0; mi < 4; mi++)
                #pragma unroll
                for (int nj = 0; nj < 4; nj++)
                    mma_f16(acc1[mi][nj], afr[mi],
                            &bfr[nj >> 1][(nj & 1) * 2], acc1[mi][nj]);
        }
    }

    // ---- GEMM2: Eh @ WTep slab (K=ke) ----
    for (int k0 = 0; k0 < ke; k0 += 32) {
        uint4 av[2], bv[2];
        #pragma unroll
        for (int t = 0; t < 2; t++) {
            int row = l_row + t * 64;
            int ga = row0 + row;
            if (ga >= M) ga = M - 1;
            av[t] = *(reinterpret_cast<const uint4*>(Eh + (size_t)ga * ke + k0) + l_c);
            bv[t] = *(reinterpret_cast<const uint4*>(WTep + (size_t)(col0 + row) * ke + k0) + l_c);
        }
        __syncthreads();
        #pragma unroll
        for (int t = 0; t < 2; t++) {
            int row = l_row + t * 64;
            uint32_t off = row * 64 + ((uint32_t)(l_c ^ ((row >> 1) & 3)) << 4);
            *reinterpret_cast<uint4*>((char*)As + off) = av[t];
            *reinterpret_cast<uint4*>((char*)Bs + off) = bv[t];
        }
        __syncthreads();
        #pragma unroll
        for (int s = 0; s < 2; s++) {
            uint32_t afr[4][4];
            #pragma unroll
            for (int mi = 0; mi < 4; mi++)
                ldsm_x4(a_row64[mi] + (((2 * s + a_hi) ^ a_sw[mi]) << 4), afr[mi]);
            uint32_t bfr[2][4];
            #pragma unroll
            for (int p = 0; p < 2; p++)
                ldsm_x4(b_row64[p] + (((2 * s + b_hi) ^ b_sw[p]) << 4), bfr[p]);
            #pragma unroll
            for (int mi = 0; mi < 4; mi++)
                #pragma unroll
                for (int nj = 0; nj < 4; nj++)
                    mma_f16(acc2[mi][nj], afr[mi],
                            &bfr[nj >> 1][(nj & 1) * 2], acc2[mi][nj]);
        }
    }

    // ---- epilogue: p = (acc1+bxp2)*(acc2+bep)*INV3 ----
    #pragma unroll
    for (int mi = 0; mi < 4; mi++) {
        int rbase = row0 + wm * 64 + mi * 16 + g;
        #pragma unroll
        for (int half = 0; half < 2; half++) {
            int r = rbase + half * 8;
            if (r >= M) continue;
            #pragma unroll
            for (int nj = 0; nj < 4; nj++) {
                int c = col0 + wn * 32 + nj * 8 + tig * 2;
                #pragma unroll
                for (int e = 0; e < 2; e++) {
                    int cc = c + e;
                    float v = (acc1[mi][nj][half * 2 + e] + bxp2[cc])
                            * (acc2[mi][nj][half * 2 + e] + bep[cc]) * INV3;
                    P[(size_t)r * 384 + cc] = v;
                }
            }
        }
    }
}

// ---------------------------------------------------------------------------
// Fused double GEMM (fp16 inputs): u = ssilu(A@W1 + sB[bidx]); hx = ssilu(u@W2+b2)+xn
// ---------------------------------------------------------------------------
__global__ void __launch_bounds__(256, 2) hgemm2h_k(
    const __half* __restrict__ A, const __half* __restrict__ WT1,
    const __half* __restrict__ WT2,
    const float* __restrict__ sB, const float* __restrict__ bias2,
    const int* __restrict__ bidx, const float* __restrict__ xnf,
    float* __restrict__ C, int M)
{
    __shared__ uint32_t Upool[8192];
    __shared__ uint32_t Bs2[2048];

    uint32_t* As = Upool;
    uint32_t* Bs = Upool + 2048;

    const int tid = threadIdx.x;
    const int warp = tid >> 5;
    const int lane = tid & 31;
    const int wm = warp & 1;
    const int wn = warp >> 1;
    const int g = lane >> 2;
    const int tig = lane & 3;
    const int row0 = blockIdx.y * 128;

    const uint32_t as_b = smem_to_u32(As);
    const uint32_t bs_b = smem_to_u32(Bs);
    const uint32_t u_b  = smem_to_u32(Upool);
    const uint32_t bs2_b = smem_to_u32(Bs2);

    const int l_row = tid >> 2;
    const int l_c = tid & 3;

    const uint32_t a_hi = lane >> 4;
    const uint32_t b_hi = (lane >> 3) & 1;
    uint32_t a_off[4], a_sw[4];
    #pragma unroll
    for (int mi = 0; mi < 4; mi++) {
        int row = wm * 64 + mi * 16 + (lane & 15);
        a_off[mi] = row * 64;
        a_sw[mi] = (row >> 1) & 3;
    }
    uint32_t b_off[2], b_sw[2];
    #pragma unroll
    for (int p = 0; p < 2; p++) {
        int row = wn * 32 + p * 16 + (lane & 7) + ((lane >> 4) ? 8 : 0);
        b_off[p] = row * 64;
        b_sw[p] = (row >> 1) & 3;
    }

    float acc[4][4][4];
    #pragma unroll
    for (int i = 0; i < 4; i++)
        #pragma unroll
        for (int j = 0; j < 4; j++)
            #pragma unroll
            for (int q = 0; q < 4; q++) acc[i][j][q] = 0.0f;

    for (int k0 = 0; k0 < 128; k0 += 32) {
        uint4 av[2], bv[2];
        #pragma unroll
        for (int t = 0; t < 2; t++) {
            int row = l_row + t * 64;
            int ga = row0 + row;
            if (ga >= M) ga = M - 1;
            av[t] = *(reinterpret_cast<const uint4*>(A + (size_t)ga * 128 + k0) + l_c);
            bv[t] = *(reinterpret_cast<const uint4*>(WT1 + (size_t)row * 128 + k0) + l_c);
        }
        __syncthreads();
        #pragma unroll
        for (int t = 0; t < 2; t++) {
            int row = l_row + t * 64;
            uint32_t off = row * 64 + ((uint32_t)(l_c ^ ((row >> 1) & 3)) << 4);
            *reinterpret_cast<uint4*>((char*)As + off) = av[t];
            *reinterpret_cast<uint4*>((char*)Bs + off) = bv[t];
        }
        __syncthreads();
        #pragma unroll
        for (int s = 0; s < 2; s++) {
            uint32_t afr[4][4];
            #pragma unroll
            for (int mi = 0; mi < 4; mi++)
                ldsm_x4(as_b + a_off[mi] + (((2 * s + a_hi) ^ a_sw[mi]) << 4), afr[mi]);
            uint32_t bfr[2][4];
            #pragma unroll
            for (int p = 0; p < 2; p++)
                ldsm_x4(bs_b + b_off[p] + (((2 * s + b_hi) ^ b_sw[p]) << 4), bfr[p]);
            #pragma unroll
            for (int mi = 0; mi < 4; mi++)
                #pragma unroll
                for (int nj = 0; nj < 4; nj++)
                    mma_f16(acc[mi][nj], afr[mi],
                            &bfr[nj >> 1][(nj & 1) * 2], acc[mi][nj]);
        }
    }

    __syncthreads();
    #pragma unroll
    for (int mi = 0; mi < 4; mi++) {
        int rloc = wm * 64 + mi * 16 + g;
        #pragma unroll
        for (int half = 0; half < 2; half++) {
            int rl = rloc + half * 8;
            int rg = row0 + rl;
            int rr = rg < M ? rg : M - 1;
            int rb = bidx[rr];
            #pragma unroll
            for (int nj = 0; nj < 4; nj++) {
                int c = wn * 32 + nj * 8 + tig * 2;
                float v0 = ssilu_f(acc[mi][nj][half * 2 + 0] + sB[(size_t)rb * 128 + c]);
                float v1 = ssilu_f(acc[mi][nj][half * 2 + 1] + sB[(size_t)rb * 128 + c + 1]);
                uint32_t chunk = (uint32_t)(c & 31) >> 3;
                uint32_t byte = (uint32_t)(c >> 5) * 8192 + rl * 64
                              + ((chunk ^ ((uint32_t)(rl >> 1) & 3)) << 4) + ((c & 7) * 2);
                *reinterpret_cast<uint32_t*>((char*)Upool + byte) = pack_h2(v0, v1);
            }
        }
    }
    __syncthreads();

    float acc2[4][4][4];
    #pragma unroll
    for (int i = 0; i < 4; i++)
        #pragma unroll
        for (int j = 0; j < 4; j++)
            #pragma unroll
            for (int q = 0; q < 4; q++) acc2[i][j][q] = 0.0f;

    for (int s4 = 0; s4 < 4; s4++) {
        uint4 bv[2];
        #pragma unroll
        for (int t = 0; t < 2; t++) {
            int row = l_row + t * 64;
            bv[t] = *(reinterpret_cast<const uint4*>(WT2 + (size_t)row * 128 + s4 * 32) + l_c);
        }
        __syncthreads();
        #pragma unroll
        for (int t = 0; t < 2; t++) {
            int row = l_row + t * 64;
            uint32_t off = row * 64 + ((uint32_t)(l_c ^ ((row >> 1) & 3)) << 4);
            *reinterpret_cast<uint4*>((char*)Bs2 + off) = bv[t];
        }
        __syncthreads();
        #pragma unroll
        for (int s = 0; s < 2; s++) {
            uint32_t afr[4][4];
            #pragma unroll
            for (int mi = 0; mi < 4; mi++)
                ldsm_x4(u_b + s4 * 8192 + a_off[mi] + (((2 * s + a_hi) ^ a_sw[mi]) << 4), afr[mi]);
            uint32_t bfr[2][4];
            #pragma unroll
            for (int p = 0; p < 2; p++)
                ldsm_x4(bs2_b + b_off[p] + (((2 * s + b_hi) ^ b_sw[p]) << 4), bfr[p]);
            #pragma unroll
            for (int mi = 0; mi < 4; mi++)
                #pragma unroll
                for (int nj = 0; nj < 4; nj++)
                    mma_f16(acc2[mi][nj], afr[mi],
                            &bfr[nj >> 1][(nj & 1) * 2], acc2[mi][nj]);
        }
    }

    #pragma unroll
    for (int mi = 0; mi < 4; mi++) {
        int rbase = row0 + wm * 64 + mi * 16 + g;
        #pragma unroll
        for (int half = 0; half < 2; half++) {
            int r = rbase + half * 8;
            if (r >= M) continue;
            #pragma unroll
            for (int nj = 0; nj < 4; nj++) {
                int c = wn * 32 + nj * 8 + tig * 2;
                #pragma unroll
                for (int e = 0; e < 2; e++) {
                    int cc = c + e;
                    float v = ssilu_f(acc2[mi][nj][half * 2 + e] + bias2[cc])
                            + xnf[(size_t)r * 128 + cc];
                    C[(size_t)r * 128 + cc] = v;
                }
            }
        }
    }
}

// ---------------------------------------------------------------------------
// mma.sync tf32 GEMM for small B-scale matrices (VB, sB)
// ---------------------------------------------------------------------------
template <int EPI>
__global__ void __launch_bounds__(256) tgemm_k(
    const float* __restrict__ A, const float* __restrict__ W,
    const float* __restrict__ bias, float* __restrict__ C,
    int M, int K, int Cc)
{
    __shared__ float As[16][136];
    __shared__ float Ws[16][136];

    const int tid = threadIdx.x;
    const int row0 = blockIdx.x * 128;
    const int col0 = blockIdx.y * 128;
    const int warp = tid >> 5;
    const int lane = tid & 31;
    const int wm = warp & 1;
    const int wn = warp >> 1;
    const int g = lane >> 2;
    const int tig = lane & 3;

    float acc[4][4][4];
    #pragma unroll
    for (int i = 0; i < 4; i++)
        #pragma unroll
        for (int j = 0; j < 4; j++)
            #pragma unroll
            for (int q = 0; q < 4; q++) acc[i][j][q] = 0.0f;

    for (int k0 = 0; k0 < K; k0 += 16) {
        #pragma unroll
        for (int t = 0; t < 2; t++) {
            int id = tid + t * 256;
            int row = id >> 2;
            int kc = (id & 3) * 4;
            float4 av;
            int grow = row0 + row;
            if (grow < M)
                av = *reinterpret_cast<const float4*>(A + (size_t)grow * K + k0 + kc);
            else
                av = make_float4(0.f, 0.f, 0.f, 0.f);
            As[kc + 0][row] = to_tf32_f(av.x);
            As[kc + 1][row] = to_tf32_f(av.y);
            As[kc + 2][row] = to_tf32_f(av.z);
            As[kc + 3][row] = to_tf32_f(av.w);
        }
        #pragma unroll
        for (int t = 0; t < 2; t++) {
            int id = tid + t * 256;
            int kr = id >> 5;
            int c4 = (id & 31) * 4;
            float4 wv = *reinterpret_cast<const float4*>(
                W + (size_t)(k0 + kr) * Cc + col0 + c4);
            Ws[kr][c4 + 0] = to_tf32_f(wv.x);
            Ws[kr][c4 + 1] = to_tf32_f(wv.y);
            Ws[kr][c4 + 2] = to_tf32_f(wv.z);
            Ws[kr][c4 + 3] = to_tf32_f(wv.w);
        }
        __syncthreads();

        #pragma unroll
        for (int s = 0; s < 2; s++) {
            const int kb = s * 8;
            uint32_t afr[4][4];
            uint32_t bfr[4][2];
            #pragma unroll
            for (int mi = 0; mi < 4; mi++) {
                int mr = wm * 64 + mi * 16 + g;
                afr[mi][0] = __float_as_uint(As[kb + tig][mr]);
                afr[mi][1] = __float_as_uint(As[kb + tig][mr + 8]);
                afr[mi][2] = __float_as_uint(As[kb + tig + 4][mr]);
                afr[mi][3] = __float_as_uint(As[kb + tig + 4][mr + 8]);
            }
            #pragma unroll
            for (int nj = 0; nj < 4; nj++) {
                int nc = wn * 32 + nj * 8 + g;
                bfr[nj][0] = __float_as_uint(Ws[kb + tig][nc]);
                bfr[nj][1] = __float_as_uint(Ws[kb + tig + 4][nc]);
            }
            #pragma unroll
            for (int mi = 0; mi < 4; mi++)
                #pragma unroll
                for (int nj = 0; nj < 4; nj++)
                    mma_tf32(acc[mi][nj], afr[mi], bfr[nj], acc[mi][nj]);
        }
        __syncthreads();
    }

    #pragma unroll
    for (int mi = 0; mi < 4; mi++) {
        int rbase = row0 + wm * 64 + mi * 16 + g;
        #pragma unroll
        for (int half = 0; half < 2; half++) {
            int r = rbase + half * 8;
            if (r >= M) continue;
            #pragma unroll
            for (int nj = 0; nj < 4; nj++) {
                int c = col0 + wn * 32 + nj * 8 + tig * 2;
                #pragma unroll
                for (int e = 0; e < 2; e++) {
                    float v = acc[mi][nj][half * 2 + e];
                    int cc = c + e;
                    if (EPI == 1) v += bias[cc];
                    C[(size_t)r * Cc + cc] = v;
                }
            }
        }
    }
}

// ---------------------------------------------------------------------------
// Node elementwise: writes xn fp32 + xnh fp16 + vecnh fp16
// ---------------------------------------------------------------------------
__global__ void node_elem_k(
    const float* __restrict__ p, const float* __restrict__ x,
    const float* __restrict__ vec, const float* __restrict__ ud,
    float* __restrict__ xn, __half* __restrict__ xnh,
    __half* __restrict__ vecnh, int N)
{
    int idx = blockIdx.x * blockDim.x + threadIdx.x;
    if (idx >= N * FDIM) return;
    int n = idx >> 7;
    int f = idx & 127;
    size_t b3 = (size_t)n * 384;

    float p1 = p[b3 + f], p2 = p[b3 + 128 + f], p3 = p[b3 + 256 + f];

    float xv = p3 + x[(size_t)n * 128 + f];
    xn[(size_t)n * 128 + f] = xv;
    xnh[(size_t)n * 128 + f] = __float2half(xv);

    float u0 = ud[n * 3 + 0], u1 = ud[n * 3 + 1], u2 = ud[n * 3 + 2];
    float v0 = vec[b3 + 0 * 128 + f];
    float v1 = vec[b3 + 1 * 128 + f];
    float v2 = vec[b3 + 2 * 128 + f];

    vecnh[b3 + 0 * 128 + f] = __float2half((p1 * v0 + p2 * u0) * INVH);
    vecnh[b3 + 1 * 128 + f] = __float2half((p1 * v1 + p2 * u1) * INVH);
    vecnh[b3 + 2 * 128 + f] = __float2half((p1 * v2 + p2 * u2) * INVH);
}

__global__ void zero_k(float* p, int n) {
    int i = blockIdx.x * blockDim.x + threadIdx.x;
    if (i < n) p[i] = 0.0f;
}

__global__ void seg_reduce_cnt_k(const float* src, const int* batch, float* dst,
                                 float* cnt, int N, int rows_per_blk)
{
    int c = threadIdx.x;
    int r0 = blockIdx.x * rows_per_blk;
    if (r0 >= N) return;
    int r1 = min(r0 + rows_per_blk, N);
    int cur = batch[r0];
    float s = 0.0f;
    int runlen = 0;
    for (int r = r0; r < r1; r++) {
        int b = batch[r];
        if (b != cur) {
            atomicAdd(&dst[(size_t)cur * 128 + c], s);
            if (c == 0) atomicAdd(&cnt[cur], (float)runlen);
            s = 0.0f;
            runlen = 0;
            cur = b;
        }
        s += src[(size_t)r * 128 + c];
        runlen++;
    }
    atomicAdd(&dst[(size_t)cur * 128 + c], s);
    if (c == 0) atomicAdd(&cnt[cur], (float)runlen);
}

__global__ void seg_reduce_k(const float* src, const int* batch, float* dst,
                             int N, int Cc, int rows_per_blk)
{
    int c = threadIdx.x;
    int r0 = blockIdx.x * rows_per_blk;
    if (r0 >= N) return;
    int r1 = min(r0 + rows_per_blk, N);
    int cur = batch[r0];
    float s = 0.0f;
    for (int r = r0; r < r1; r++) {
        int b = batch[r];
        if (b != cur) {
            atomicAdd(&dst[(size_t)cur * Cc + c], s);
            s = 0.0f;
            cur = b;
        }
        s += src[(size_t)r * Cc + c];
    }
    atomicAdd(&dst[(size_t)cur * Cc + c], s);
}

// ---------------------------------------------------------------------------
// Fused global phase (validated in R8)
// ---------------------------------------------------------------------------
__global__ void __launch_bounds__(128) global_k(
    const float* __restrict__ sum_x, const float* __restrict__ sum_vec,
    const float* __restrict__ cnt,
    const float* __restrict__ scalar_l, const float* __restrict__ vector_l,
    const float* __restrict__ W_sg1, const float* __restrict__ b_sg1,
    const float* __restrict__ W_sg2, const float* __restrict__ b_sg2,
    const float* __restrict__ W_vg, const float* __restrict__ W_vp,
    const float* __restrict__ W_lp1, const float* __restrict__ b_lp1,
    const float* __restrict__ W_lp2, const float* __restrict__ b_lp2,
    const float* __restrict__ W_ml,
    float* __restrict__ out_sl, float* __restrict__ out_vl,
    float* __restrict__ out_ld)
{
    int b = blockIdx.x;
    int f = threadIdx.x;
    __shared__ float s_g[256];
    __shared__ float s_t[128];
    __shared__ float s_av[3][128];
    __shared__ float s_vl[3][128];
    __shared__ float s_h1[3][128];
    __shared__ float s_red[12];

    float invc = 1.0f / fmaxf(cnt[b], 1.0f);
    size_t bf = (size_t)b * 128 + f;
    float sclf = scalar_l[bf];
    s_g[f] = sum_x[bf] * invc;
    s_g[128 + f] = sclf;
    float vlg[3];
    #pragma unroll
    for (int d = 0; d < 3; d++) {
        size_t o = (size_t)b * 384 + d * 128 + f;
        vlg[d] = vector_l[o];
        s_av[d][f] = sum_vec[o] * invc + vlg[d];
    }
    __syncthreads();

    float acc = b_sg1[f];
    #pragma unroll 8
    for (int k = 0; k < 256; k++) acc += s_g[k] * W_sg1[k * 128 + f];
    s_t[f] = ssilu_f(acc);
    __syncthreads();

    acc = b_sg2[f];
    #pragma unroll 8
    for (int k = 0; k < 128; k++) acc += s_t[k] * W_sg2[k * 128 + f];
    float sl = sclf + ssilu_f(acc);

    float vl[3];
    #pragma unroll
    for (int d = 0; d < 3; d++) {
        float a = 0.0f;
        #pragma unroll 8
        for (int k = 0; k < 128; k++) a += s_av[d][k] * W_vg[k * 128 + f];
        vl[d] = vlg[d] + a;
        s_vl[d][f] = vl[d];
    }
    __syncthreads();

    float vn = 1e-8f;
    #pragma unroll
    for (int d = 0; d < 3; d++) {
        float h1 = 0.0f, h2 = 0.0f;
        #pragma unroll 8
        for (int k = 0; k < 128; k++) {
            float t = s_vl[d][k];
            h1 += t * W_vp[k * 256 + f];
            h2 += t * W_vp[k * 256 + 128 + f];
        }
        s_h1[d][f] = h1;
        vn += h2 * h2;
    }
    s_g[f] = sl;
    s_g[128 + f] = sqrtf(vn);
    __syncthreads();

    acc = b_lp1[f];
    #pragma unroll 8
    for (int k = 0; k < 256; k++) acc += s_g[k] * W_lp1[k * 128 + f];
    s_t[f] = ssilu_f(acc);
    __syncthreads();

    float s1 = b_lp2[f], s2 = b_lp2[128 + f], s3 = b_lp2[256 + f];
    #pragma unroll 4
    for (int k = 0; k < 128; k++) {
        float t = s_t[k];
        s1 += t * W_lp2[k * 384 + f];
        s2 += t * W_lp2[k * 384 + 128 + f];
        s3 += t * W_lp2[k * 384 + 256 + f];
    }
    out_sl[bf] = s2 + sl * tanhf(s3);

    float wml = W_ml[f];
    float part[3];
    #pragma unroll
    for (int d = 0; d < 3; d++) {
        float v = s1 * s_h1[d][f] + vl[d];
        out_vl[(size_t)b * 384 + d * 128 + f] = v;
        part[d] = v * wml;
    }
    #pragma unroll
    for (int d = 0; d < 3; d++)
        #pragma unroll
        for (int o = 16; o; o >>= 1)
            part[d] += __shfl_down_sync(0xffffffff, part[d], o);
    int w = f >> 5, ln = f & 31;
    if (ln == 0) {
        #pragma unroll
        for (int d = 0; d < 3; d++) s_red[d * 4 + w] = part[d];
    }
    __syncthreads();
    if (f < 3)
        out_ld[b * 3 + f] = s_red[f * 4] + s_red[f * 4 + 1]
                          + s_red[f * 4 + 2] + s_red[f * 4 + 3];
}

// ---------------------------------------------------------------------------
extern "C" void kernel_launch(void* const* d_in, const int* in_sizes, int n_in,
                              void* d_out, int out_size)
{
    const float* x        = (const float*)d_in[0];
    const float* scalar_l = (const float*)d_in[1];
    const float* vec      = (const float*)d_in[2];
    const float* vector_l = (const float*)d_in[3];
    const float* edge_f   = (const float*)d_in[4];
    const float* edge_ud  = (const float*)d_in[5];
    const int*   batch    = (const int*)d_in[6];
    const float* W_sg1 = (const float*)d_in[7];  const float* b_sg1 = (const float*)d_in[8];
    const float* W_sg2 = (const float*)d_in[9];  const float* b_sg2 = (const float*)d_in[10];
    const float* W_sl1 = (const float*)d_in[11]; const float* b_sl1 = (const float*)d_in[12];
    const float* W_sl2 = (const float*)d_in[13]; const float* b_sl2 = (const float*)d_in[14];
    const float* W_vg  = (const float*)d_in[15];
    const float* W_vl  = (const float*)d_in[16];
    const float* W_xp1 = (const float*)d_in[17]; const float* b_xp1 = (const float*)d_in[18];
    const float* W_xp2 = (const float*)d_in[19]; const float* b_xp2 = (const float*)d_in[20];
    const float* W_ep  = (const float*)d_in[21]; const float* b_ep  = (const float*)d_in[22];
    const float* W_vp  = (const float*)d_in[23];
    const float* W_lp1 = (const float*)d_in[24]; const float* b_lp1 = (const float*)d_in[25];
    const float* W_lp2 = (const float*)d_in[26]; const float* b_lp2 = (const float*)d_in[27];
    const float* W_ml  = (const float*)d_in[28];

    const int N = in_sizes[0] / FDIM;
    const int B = in_sizes[1] / FDIM;
    const int ke = in_sizes[4] / N;   // 64

    float* base = nullptr;
    cudaGetSymbolAddress((void**)&base, g_buf);

    const size_t NF = (size_t)N * FDIM;
    const size_t NH = (size_t)N * 128;   // halves per [N,128]

    float* p_buf  = base;                 // [N,384] fp32
    float* xn_buf = base + 3 * NF;        // [N,128] fp32
    __half* hb    = (__half*)(base + 4 * NF);
    __half* th    = hb;                   // [N,128]
    __half* xh    = hb + NH;              // [N,128]
    __half* xnh   = hb + 2 * NH;          // [N,128]
    __half* vecnh = hb + 3 * NH;          // [3N,128]
    __half* edgeh = hb + 6 * NH;          // [N,ke]
    __half* wh    = hb + 6 * NH + (size_t)N * ke;
    __half* wh_xp1 = wh;
    __half* wh_xp2 = wh + 16384;
    __half* wh_ep  = wh + 65536;
    __half* wh_sl1 = wh + 65536 + 384 * ke;
    __half* wh_sl2 = wh_sl1 + 16384;
    __half* wh_vl  = wh_sl2 + 16384;
    float* smf = (float*)(wh_vl + 16384 + 16);
    float* sB      = smf;                      // B*128
    float* sum_x   = sB + (size_t)B * 128;     // B*128
    float* sum_vec = sum_x + (size_t)B * 128;  // B*384
    float* cnt     = sum_vec + (size_t)B * 384;// B
    float* VB      = cnt + B + 64;             // 3B*128

    float* out = (float*)d_out;
    const size_t o0 = 0;
    const size_t o1 = NF;
    const size_t o2 = o1 + 3 * NF;
    const size_t o3 = o2 + (size_t)B * 128;
    const size_t o4 = o3 + (size_t)B * 384;

    const int rT_N  = (N + 127) / 128;
    const int rT_3N = (3 * N + 127) / 128;
    const int gM_B  = (B + 127) / 128;
    const int gM_3B = (3 * B + 127) / 128;

    // 0: all weight transposes -> fp16
    {
        int tot = 16384 * 4 + 49152 + 384 * ke;
        wtrans_all_k<<<(tot + 255) / 256, 256>>>(W_xp1, W_xp2, W_ep, W_sl1, W_sl2, W_vl, wh, ke);
    }
    // 1-2: input conversions
    f2h_k<<<((int)(NH / 8) + 255) / 256, 256>>>(x, xh, (int)NH);
    f2h_k<<<((N * ke / 8) + 255) / 256, 256>>>(edge_f, edgeh, N * ke);
    // 3-4: small B-scale GEMMs (tf32)
    tgemm_k<0><<<dim3(gM_3B, 1), 256>>>(vector_l, W_vl, nullptr, VB, 3 * B, 128, 128);
    tgemm_k<1><<<dim3(gM_B, 1), 256>>>(scalar_l, W_sl1 + 128 * 128, b_sl1, sB, B, 128, 128);
    // 5: t = ssilu(x @ W_xp1 + b_xp1) -> fp16
    hgemmh_k<2><<<dim3(1, rT_N), 256>>>(xh, wh_xp1, b_xp1, th, N, 128, 128, nullptr, nullptr, nullptr);
    // 6: p = (t@W_xp2+b)(edge@W_ep+b)*INV3
    pgemm_k<<<dim3(3, rT_N), 256>>>(th, edgeh, wh_xp2, wh_ep, b_xp2, b_ep, p_buf, N, ke);
    // 7: node elementwise
    node_elem_k<<<(N * FDIM + 255) / 256, 256>>>(p_buf, x, vec, edge_ud, xn_buf, xnh, vecnh, N);
    // 8: hx (fused double GEMM)
    hgemm2h_k<<<dim3(1, rT_N), 256>>>(xnh, wh_sl1, wh_sl2, sB, b_sl2, batch, xn_buf, out + o0, N);
    // 9: hvec = vecn @ W_vl + vecn + VB[batch]
    hgemmh_k<7><<<dim3(1, rT_3N), 256>>>(vecnh, wh_vl, nullptr, out + o1, 3 * N, 128, 128, vecnh, VB, batch);
    // 10-12: segment reduction
    {
        int nz = B * 128 + B * 384 + B;
        zero_k<<<(nz + 255) / 256, 256>>>(sum_x, nz);
        seg_reduce_cnt_k<<<(N + 127) / 128, 128>>>(out + o0, batch, sum_x, cnt, N, 128);
        seg_reduce_k<<<(N + 63) / 64, 384>>>(out + o1, batch, sum_vec, N, 384, 64);
    }
    // 13: fused global phase
    global_k<<<B, 128>>>(sum_x, sum_vec, cnt, scalar_l, vector_l,
                         W_sg1, b_sg1, W_sg2, b_sg2, W_vg, W_vp,
                         W_lp1, b_lp1, W_lp2, b_lp2, W_ml,
                         out + o2, out + o3, out + o4);
}